// round 6
// baseline (speedup 1.0000x reference)
#include <cuda_runtime.h>
#include <math.h>
#include <stdint.h>

#define NV    8192
#define DEG   16
#define EMBD  512
#define NPCC  256
#define NL    257
#define H2D   400
#define TPB   512

// ---------------- persistent device scratch ----------------
__device__ __align__(16) float g_z[(size_t)NV * EMBD];
__device__ __align__(16) float g_TI1[128 * 512 * 4];   // fc1^T interleaved
__device__ __align__(16) float g_TIz[128 * 512 * 4];   // W[:512] interleaved (z cols)
__device__ __align__(16) float g_TI2[128 * 512 * 4];   // fc2^T interleaved, rank-padded cols
__device__ __align__(16) float g_TI3[128 * 512 * 4];   // fc3^T interleaved, rank-padded cols + permuted k
__device__ float g_red[16 * 4];

// ---------------- smem layout (bytes) ----------------
#define OFF_TRI     0        // float4[16]
#define OFF_MBAR    256      // u64[3] (h1, h2, tri)
#define OFF_H       288      // float[16*512]
#define OFF_NE      33056    // float[512]
#define OFF_PART    35104    // float[512]
#define OFF_PARTZ   37152    // float[512]
#define OFF_A2      39200    // float[512]
#define OFF_H1BUF   41248    // float[512]
#define OFF_H2P     43296    // float[512]  (permuted h2, pads zero)
#define OFF_B1      45344    // float[64]
#define OFF_B2      45600    // float[64]
#define OFF_B3      45856    // float[64]
#define OFF_E       46112    // float[16]
#define OFF_LOC     46176    // float[64]
#define OFF_RED     46432    // float[16]
#define OFF_COLORS  46496    // int[8192]
#define OFF_NBRC    79264    // int[16]
#define OFF_MISC    79328    // int[4]
#define SMEM_BYTES  79360

__device__ __forceinline__ float wsum(float v) {
#pragma unroll
    for (int o = 16; o; o >>= 1) v += __shfl_xor_sync(0xffffffffu, v, o);
    return v;
}
__device__ __forceinline__ float dot4(float4 a, float4 b) {
    return a.x * b.x + a.y * b.y + a.z * b.z + a.w * b.w;
}
__device__ __forceinline__ uint32_t s2u(const void* p) {
    uint32_t a;
    asm("{ .reg .u64 t; cvta.to.shared.u64 t, %1; cvt.u32.u64 %0, t; }" : "=r"(a) : "l"(p));
    return a;
}
__device__ __forceinline__ uint32_t mapa_u32(uint32_t laddr, uint32_t rnk) {
    uint32_t r;
    asm("mapa.shared::cluster.u32 %0, %1, %2;" : "=r"(r) : "r"(laddr), "r"(rnk));
    return r;
}
__device__ __forceinline__ void sts_cl_f32(uint32_t a, float v) {
    asm volatile("st.shared::cluster.f32 [%0], %1;" :: "r"(a), "f"(v) : "memory");
}
__device__ __forceinline__ void sts_cl_f4(uint32_t a, float4 v) {
    asm volatile("st.shared::cluster.v4.f32 [%0], {%1,%2,%3,%4};"
                 :: "r"(a), "f"(v.x), "f"(v.y), "f"(v.z), "f"(v.w) : "memory");
}
__device__ __forceinline__ void mbar_init(uint32_t a, uint32_t cnt) {
    asm volatile("mbarrier.init.shared.b64 [%0], %1;" :: "r"(a), "r"(cnt) : "memory");
}
__device__ __forceinline__ void mbar_arrive_cl(uint32_t ra) {
    asm volatile("mbarrier.arrive.release.cluster.shared::cluster.b64 _, [%0];" :: "r"(ra) : "memory");
}
__device__ __forceinline__ void fence_cl() {
    asm volatile("fence.acq_rel.cluster;" ::: "memory");
}
#define MBAR_WAIT_CL(addr, par) do { \
    uint32_t _d; \
    asm volatile("{\n\t.reg .pred p;\n\t" \
        "mbarrier.try_wait.parity.acquire.cluster.shared::cta.b64 p, [%1], %2;\n\t" \
        "selp.b32 %0, 1, 0, p;\n\t}" : "=r"(_d) : "r"(addr), "r"(par) : "memory"); \
    if (!_d) { \
        asm volatile("{\n\t.reg .pred P1;\n\t" \
            "W%=:\n\t" \
            "mbarrier.try_wait.parity.acquire.cluster.shared::cta.b64 P1, [%0], %1, 0x989680;\n\t" \
            "@P1 bra.uni D%=;\n\t" \
            "bra.uni W%=;\n\t" \
            "D%=:\n\t}" :: "r"(addr), "r"(par) : "memory"); \
    } \
} while (0)

#define CLUSTER_SYNC() do { \
    asm volatile("barrier.cluster.arrive.aligned;" ::: "memory"); \
    asm volatile("barrier.cluster.wait.aligned;"   ::: "memory"); } while (0)

// column-GEMV: Kq float4 k-steps, weights at float4-stride 512
template<int Kq>
__device__ __forceinline__ float colgemv(const float4* __restrict__ w4,
                                         const float4* __restrict__ in4) {
    float ax = 0.f, ay = 0.f, az = 0.f, aw = 0.f;
#pragma unroll
    for (int i = 0; i < Kq; i++) {
        float4 w = w4[(size_t)i * 512];
        float4 x = in4[i];
        ax = fmaf(w.x, x.x, ax); ay = fmaf(w.y, x.y, ay);
        az = fmaf(w.z, x.z, az); aw = fmaf(w.w, x.w, aw);
    }
    return (ax + ay) + (az + aw);
}

template<int C>
__device__ __forceinline__ void gc_body(
    const int* __restrict__ adj, const float* __restrict__ W,
    const float* __restrict__ a, const float* __restrict__ fc1w,
    const float* __restrict__ fc1b, const float* __restrict__ fc2w,
    const float* __restrict__ fc2b, const float* __restrict__ fc3w,
    const float* __restrict__ fc3b, const int* __restrict__ baseline,
    float* __restrict__ out, int out_size)
{
    constexpr int O1pad = 512 / C;            // cols per CTA (padded), 32 / 64
    constexpr int Kq    = 128 / C;            // float4 k-steps per part
    constexpr int Ofr   = H2D / C;            // real fc2 cols per CTA: 25 / 50
    constexpr int O3r   = (C == 16) ? 17 : 33;

    extern __shared__ __align__(16) unsigned char smem[];
    float4* tribuf  = (float4*)(smem + OFF_TRI);
    float*  sh_h    = (float*)(smem + OFF_H);
    float*  sh_ne   = (float*)(smem + OFF_NE);
    float*  sh_part = (float*)(smem + OFF_PART);
    float*  sh_ptz  = (float*)(smem + OFF_PARTZ);
    float*  sh_a2   = (float*)(smem + OFF_A2);
    float*  h1buf   = (float*)(smem + OFF_H1BUF);
    float*  h2p     = (float*)(smem + OFF_H2P);
    float*  sh_b1   = (float*)(smem + OFF_B1);
    float*  sh_b2   = (float*)(smem + OFF_B2);
    float*  sh_b3   = (float*)(smem + OFF_B3);
    float*  sh_e    = (float*)(smem + OFF_E);
    float*  sh_loc  = (float*)(smem + OFF_LOC);
    float*  sh_red  = (float*)(smem + OFF_RED);
    int*    sh_colors = (int*)(smem + OFF_COLORS);
    int*    sh_nbrc   = (int*)(smem + OFF_NBRC);
    int*    sh_misc   = (int*)(smem + OFF_MISC);

    const uint32_t sbase  = s2u(smem);
    const uint32_t A_H1   = sbase + OFF_H1BUF;
    const uint32_t A_H2P  = sbase + OFF_H2P;
    const uint32_t A_TRI  = sbase + OFF_TRI;
    const uint32_t MB_H1  = sbase + OFF_MBAR;
    const uint32_t MB_H2  = sbase + OFF_MBAR + 8;
    const uint32_t MB_TRI = sbase + OFF_MBAR + 16;

    const int rank = blockIdx.x;
    const int tid  = threadIdx.x;
    const int warp = tid >> 5, lane = tid & 31;
    const int gtid = rank * TPB + tid;
    const int GS   = C * TPB;

    float lpp = 0.f, regv = 0.f;

    // ---------------- per-launch init ----------------
    if (tid == 0) {
        mbar_init(MB_H1, C);
        mbar_init(MB_H2, C);
        mbar_init(MB_TRI, C);
        sh_misc[0] = 1;
    }
    {
        float4 z4 = make_float4(0.f, 0.f, 0.f, 0.f);
        float4* zp = (float4*)g_z;
        const size_t nz4 = (size_t)NV * EMBD / 4;
        for (size_t i = gtid; i < nz4; i += GS) zp[i] = z4;
    }
    for (int d = gtid; d < 128 * 512 * 4; d += GS) {
        int c4 = d & 3, col = (d >> 2) & 511, kq = d >> 11;
        int k  = kq * 4 + c4;
        g_TI1[d] = fc1w[col * 512 + k];
        g_TIz[d] = W[k * 512 + col];
        int rnk = col / O1pad, jl = col % O1pad;
        int j2 = rnk * Ofr + jl;
        g_TI2[d] = (jl < Ofr) ? fc2w[j2 * 512 + k] : 0.f;
        int j3 = rnk * O3r + jl;
        int rs = k / O1pad, is = k % O1pad;
        g_TI3[d] = (jl < O3r && j3 < NL && is < Ofr) ? fc3w[j3 * H2D + rs * Ofr + is] : 0.f;
    }
    for (int i = tid; i < NV; i += TPB) sh_colors[i] = (i == 0) ? 0 : -1;
    for (int i = tid; i < EMBD; i += TPB) sh_a2[i] = a[EMBD + i];
    if (tid < 512) h2p[tid] = 0.f;             // pads stay 0 forever
    if (tid < 64) sh_loc[tid] = -INFINITY;     // slots >= O1pad stay -inf
    if (tid < O1pad) sh_b1[tid] = fc1b[rank * O1pad + tid];
    if (tid < Ofr)   sh_b2[tid] = fc2b[rank * Ofr + tid];
    if (tid < O3r) { int j = rank * O3r + tid; sh_b3[tid] = (j < NL) ? fc3b[j] : 0.f; }

    // ---------------- Frobenius norms ----------------
    {
        float s[4] = {0.f, 0.f, 0.f, 0.f};
        for (int i = gtid; i < 768 * 512; i += GS) { float x = W[i];    s[0] += x * x; }
        for (int i = gtid; i < 512 * 512; i += GS) { float x = fc1w[i]; s[1] += x * x; }
        for (int i = gtid; i < 400 * 512; i += GS) { float x = fc2w[i]; s[2] += x * x; }
        for (int i = gtid; i < 257 * 400; i += GS) { float x = fc3w[i]; s[3] += x * x; }
#pragma unroll
        for (int m = 0; m < 4; m++) {
            float w = wsum(s[m]);
            __syncthreads();
            if (lane == 0) sh_red[warp] = w;
            __syncthreads();
            if (warp == 0) {
                float v2 = (lane < 16) ? sh_red[lane] : 0.f;
                v2 = wsum(v2);
                if (lane == 0) g_red[rank * 4 + m] = v2;
            }
            __syncthreads();
        }
    }
    CLUSTER_SYNC();   // init + mbarriers + norms visible cluster-wide

    if (rank == 0 && tid == 0) {
        for (int c = 0; c < 4; c++) {
            float ssq = 0.f;
            for (int r = 0; r < C; r++) ssq += __ldcg(&g_red[r * 4 + c]);
            regv += sqrtf(ssq);
        }
    }

    const float4* ne4 = (const float4*)sh_ne;
    int u = adj[DEG + warp];   // prefetched neighbor for v=1

    // ======================= sequential scan =======================
    for (int v = 1; v < NV; ++v) {
        const int ph = (v & 1) ^ 1;   // mbarrier wait parity for this step

        // ---- Stage A: 16 neighbor rows, one per warp (h_self == 0) ----
        {
            int c = sh_colors[u];
            if (lane == 0) sh_nbrc[warp] = c;
            const float4* z4 = (const float4*)(g_z + (size_t)u * EMBD);
            const float4* w4 = (c >= 0) ? (const float4*)(W + (size_t)(EMBD + c) * EMBD)
                                        : (const float4*)0;
            float4* hrow = (float4*)(sh_h + warp * EMBD);
            float d2 = 0.f;
#pragma unroll
            for (int i = 0; i < 4; i++) {
                int idx = lane + 32 * i;
                float4 hv = __ldcg(z4 + idx);
                if (w4) { float4 wv = w4[idx]; hv.x += wv.x; hv.y += wv.y; hv.z += wv.z; hv.w += wv.w; }
                hrow[idx] = hv;
                d2 += dot4(hv, ((const float4*)sh_a2)[idx]);
            }
            d2 = wsum(d2);
            if (lane == 0) sh_e[warp] = d2;
        }
        __syncthreads();   // bar1

        // ---- softmax (replicated per warp) + new_e = elu(attn @ h) ----
        {
            float ev;
            if (lane == 0) ev = 0.f;
            else if (lane < 17) { float t = sh_e[lane - 1]; ev = (t > 0.f) ? t : 0.2f * t; }
            else ev = -INFINITY;
            float m = ev;
#pragma unroll
            for (int o = 16; o; o >>= 1) m = fmaxf(m, __shfl_xor_sync(0xffffffffu, m, o));
            float p = (lane < 17) ? expf(ev - m) : 0.f;
            float s = wsum(p);
            float attn = p / s;
            float acc = 0.f;
#pragma unroll
            for (int t = 1; t < 17; t++)
                acc += __shfl_sync(0xffffffffu, attn, t) * sh_h[(t - 1) * EMBD + tid];
            sh_ne[tid] = (acc > 0.f) ? acc : expm1f(acc);
        }
        __syncthreads();   // bar2

        // ---- P1 partials: fc1 ----
        {
            int p = tid / O1pad, jl = tid % O1pad;
            sh_part[tid] = colgemv<Kq>((const float4*)g_TI1 + (size_t)(p * Kq) * 512
                                        + rank * O1pad + jl, ne4 + p * Kq);
        }
        __syncthreads();   // bar3

        // ---- h1 finalize + remote stores, then z partials ----
        if (tid < O1pad) {
            float sum = 0.f;
#pragma unroll
            for (int q = 0; q < C; q++) sum += sh_part[q * O1pad + tid];
            float h = sum + sh_b1[tid];
            h = (h > 0.f) ? h : 0.01f * h;
            uint32_t off = A_H1 + (rank * O1pad + tid) * 4;
#pragma unroll
            for (int c = 0; c < C; c++) sts_cl_f32(mapa_u32(off, c), h);
        }
        {
            int p = tid / O1pad, jl = tid % O1pad;
            sh_ptz[tid] = colgemv<Kq>((const float4*)g_TIz + (size_t)(p * Kq) * 512
                                       + rank * O1pad + jl, ne4 + p * Kq);
        }
        __syncthreads();   // bar4 (h1 stores + z partials ordered)

        if (warp == 0 && lane < C) { fence_cl(); mbar_arrive_cl(mapa_u32(MB_H1, lane)); }
        {
            int zt = tid - 64;
            if (zt >= 0 && zt < O1pad) {
                float sum = 0.f;
#pragma unroll
                for (int q = 0; q < C; q++) sum += sh_ptz[q * O1pad + zt];
                __stcg(&g_z[(size_t)v * EMBD + rank * O1pad + zt], sum);
            }
        }
        MBAR_WAIT_CL(MB_H1, ph);

        // ---- P2 partials: fc2 over full h1 (local smem) ----
        {
            int p = tid / O1pad, jl = tid % O1pad;
            sh_part[tid] = colgemv<Kq>((const float4*)g_TI2 + (size_t)(p * Kq) * 512
                                        + rank * O1pad + jl, (const float4*)h1buf + p * Kq);
        }
        __syncthreads();   // bar5

        if (tid < Ofr) {
            float sum = 0.f;
#pragma unroll
            for (int q = 0; q < C; q++) sum += sh_part[q * O1pad + tid];
            float h = sum + sh_b2[tid];
            h = (h > 0.f) ? h : 0.01f * h;
            uint32_t off = A_H2P + (rank * O1pad + tid) * 4;   // permuted slot
#pragma unroll
            for (int c = 0; c < C; c++) sts_cl_f32(mapa_u32(off, c), h);
        }
        __syncthreads();   // bar5b

        if (warp == 0 && lane < C) { fence_cl(); mbar_arrive_cl(mapa_u32(MB_H2, lane)); }
        MBAR_WAIT_CL(MB_H2, ph);

        // ---- P3 partials: fc3 over permuted h2 (local smem) ----
        {
            int p = tid / O1pad, jl = tid % O1pad;
            sh_part[tid] = colgemv<Kq>((const float4*)g_TI3 + (size_t)(p * Kq) * 512
                                        + rank * O1pad + jl, (const float4*)h2p + p * Kq);
        }
        __syncthreads();   // bar6

        if (tid < O1pad) {
            float sum = 0.f;
#pragma unroll
            for (int q = 0; q < C; q++) sum += sh_part[q * O1pad + tid];
            int j = rank * O3r + tid;
            float mlv = -INFINITY;
            if (tid < O3r && j < NL) {
                float L = sum + sh_b3[tid];
                int nused = sh_misc[0];
                bool irrel = (j >= nused) && (j < NPCC);
                bool am = false;
#pragma unroll
                for (int t = 0; t < 16; t++) am |= (sh_nbrc[t] == j);
                mlv = (irrel || am) ? -INFINITY : L;
            }
            sh_loc[tid] = mlv;
        }
        __syncthreads();   // bar6b

        if (warp == 0) {
            float v1 = sh_loc[lane];      int i1 = lane;
            float v2 = sh_loc[lane + 32]; int i2 = lane + 32;
            if (v2 > v1) { v1 = v2; i1 = i2; }
            float rv = v1; int ri = i1;
#pragma unroll
            for (int o = 16; o; o >>= 1) {
                float ov = __shfl_xor_sync(0xffffffffu, rv, o);
                int   oi = __shfl_xor_sync(0xffffffffu, ri, o);
                if (ov > rv || (ov == rv && oi < ri)) { rv = ov; ri = oi; }
            }
            float t0 = (sh_loc[lane]      == -INFINITY) ? 0.f : expf(sh_loc[lane]      - rv);
            float t1 = (sh_loc[lane + 32] == -INFINITY) ? 0.f : expf(sh_loc[lane + 32] - rv);
            float lsum = wsum(t0 + t1);
            if (rv == -INFINITY) lsum = 0.f;
            if (lane < C) {
                fence_cl();   // also releases this CTA's g_z stores (bar-chain)
                float4 tri = make_float4(rv, lsum, __int_as_float(rank * O3r + ri), 0.f);
                sts_cl_f4(mapa_u32(A_TRI + rank * 16, lane), tri);
                mbar_arrive_cl(mapa_u32(MB_TRI, lane));
            }
        }
        if (v + 1 < NV) u = adj[(v + 1) * DEG + warp];   // prefetch next step
        MBAR_WAIT_CL(MB_TRI, ph);

        // ---- E: combine (replicated), commit ----
        if (warp == 0) {
            float cv = -INFINITY, cs = 0.f; int ci = 0x7fffffff;
            if (lane < C) {
                float4 t4 = tribuf[lane];
                cv = t4.x; cs = t4.y; ci = __float_as_int(t4.z);
            }
            float mv = cv; int mi = ci;
#pragma unroll
            for (int o = 16; o; o >>= 1) {
                float ov = __shfl_xor_sync(0xffffffffu, mv, o);
                int   oi = __shfl_xor_sync(0xffffffffu, mi, o);
                if (ov > mv || (ov == mv && oi < mi)) { mv = ov; mi = oi; }
            }
            float term = (lane < C && cv != -INFINITY) ? cs * expf(cv - mv) : 0.f;
            float gsum = wsum(term);
            if (lane == 0) {
                int cur    = sh_misc[0];
                int isnew  = (mi == NPCC) ? 1 : 0;
                sh_colors[v] = isnew ? cur : mi;
                sh_misc[0] = cur + isnew;
                lpp += logf(1.f / gsum + 1e-8f) + 18.420680743952367f;
            }
        }
        __syncthreads();   // bar7: colors/nused published locally
    }

    // ---------------- output: [colors..., loss] ----------------
    for (int i = gtid; i < NV && i < out_size; i += GS)
        out[i] = (float)sh_colors[i];
    if (rank == 0 && tid == 0 && out_size > NV) {
        float loss = ((float)sh_misc[0] - (float)baseline[0]) * lpp / (float)NV + 0.05f * regv;
        out[NV] = loss;
    }
}

#define PARAMS const int* adj, const float* W, const float* a, const float* fc1w, \
               const float* fc1b, const float* fc2w, const float* fc2b,           \
               const float* fc3w, const float* fc3b, const int* baseline,         \
               float* out, int out_size
#define ARGS adj, W, a, fc1w, fc1b, fc2w, fc2b, fc3w, fc3b, baseline, out, out_size

__global__ void __launch_bounds__(TPB, 1)
gc_k16(PARAMS) { gc_body<16>(ARGS); }

__global__ void __launch_bounds__(TPB, 1) __cluster_dims__(8, 1, 1)
gc_k8(PARAMS) { gc_body<8>(ARGS); }

extern "C" void kernel_launch(void* const* d_in, const int* in_sizes, int n_in,
                              void* d_out, int out_size) {
    (void)in_sizes; (void)n_in;
    const int*   adj  = (const int*)d_in[0];
    const float* W    = (const float*)d_in[1];
    const float* a    = (const float*)d_in[2];
    const float* fc1w = (const float*)d_in[3];
    const float* fc1b = (const float*)d_in[4];
    const float* fc2w = (const float*)d_in[5];
    const float* fc2b = (const float*)d_in[6];
    const float* fc3w = (const float*)d_in[7];
    const float* fc3b = (const float*)d_in[8];
    const int*   bl   = (const int*)d_in[9];
    float* out = (float*)d_out;

    cudaFuncSetAttribute(gc_k16, cudaFuncAttributeNonPortableClusterSizeAllowed, 1);
    cudaFuncSetAttribute(gc_k16, cudaFuncAttributeMaxDynamicSharedMemorySize, SMEM_BYTES);
    cudaFuncSetAttribute(gc_k8,  cudaFuncAttributeMaxDynamicSharedMemorySize, SMEM_BYTES);
    (void)cudaGetLastError();

    int maxC = 0;
    cudaLaunchConfig_t q = {};
    q.gridDim = {16, 1, 1}; q.blockDim = {TPB, 1, 1};
    q.dynamicSmemBytes = SMEM_BYTES; q.stream = 0;
    cudaError_t qe = cudaOccupancyMaxPotentialClusterSize(&maxC, gc_k16, &q);
    (void)cudaGetLastError();

    if (qe == cudaSuccess && maxC >= 16) {
        cudaLaunchConfig_t cfg = {};
        cfg.gridDim = {16, 1, 1}; cfg.blockDim = {TPB, 1, 1};
        cfg.dynamicSmemBytes = SMEM_BYTES; cfg.stream = 0;
        cudaLaunchAttribute at[1];
        at[0].id = cudaLaunchAttributeClusterDimension;
        at[0].val.clusterDim = {16, 1, 1};
        cfg.attrs = at; cfg.numAttrs = 1;
        cudaLaunchKernelEx(&cfg, gc_k16, adj, W, a, fc1w, fc1b, fc2w, fc2b,
                           fc3w, fc3b, bl, out, out_size);
    } else {
        gc_k8<<<8, TPB, SMEM_BYTES>>>(adj, W, a, fc1w, fc1b, fc2w, fc2b,
                                      fc3w, fc3b, bl, out, out_size);
    }
}

// round 7
// speedup vs baseline: 1.0405x; 1.0405x over previous
#include <cuda_runtime.h>
#include <math.h>
#include <stdint.h>

#define NV    8192
#define DEG   16
#define EMBD  512
#define NPCC  256
#define NL    257
#define H2D   400
#define TPB   256
#define DEFERC (-3)

// ---------------- persistent device scratch ----------------
__device__ __align__(16) float g_z[(size_t)NV * EMBD];
__device__ __align__(16) float g_TIz[512 * 512];      // z-col weights [kq][col][c4]
__device__ __align__(16) float g_TI1g[262144];        // fallback (C=8) fc1 slices
__device__ __align__(16) float g_TI2g[204800];        // fallback fc2
__device__ __align__(16) float g_TI3g[135168];        // fallback fc3
__device__ float g_red[16 * 4];

__device__ __forceinline__ float wsum(float v) {
#pragma unroll
    for (int o = 16; o; o >>= 1) v += __shfl_xor_sync(0xffffffffu, v, o);
    return v;
}
__device__ __forceinline__ float dot4(float4 a, float4 b) {
    return a.x * b.x + a.y * b.y + a.z * b.z + a.w * b.w;
}
__device__ __forceinline__ uint32_t s2u(const void* p) {
    uint32_t a;
    asm("{ .reg .u64 t; cvta.to.shared.u64 t, %1; cvt.u32.u64 %0, t; }" : "=r"(a) : "l"(p));
    return a;
}
__device__ __forceinline__ uint32_t mapa_u32(uint32_t laddr, uint32_t rnk) {
    uint32_t r;
    asm("mapa.shared::cluster.u32 %0, %1, %2;" : "=r"(r) : "r"(laddr), "r"(rnk));
    return r;
}
__device__ __forceinline__ void sts_cl_f32(uint32_t a, float v) {
    asm volatile("st.shared::cluster.f32 [%0], %1;" :: "r"(a), "f"(v) : "memory");
}
__device__ __forceinline__ void sts_cl_f4(uint32_t a, float4 v) {
    asm volatile("st.shared::cluster.v4.f32 [%0], {%1,%2,%3,%4};"
                 :: "r"(a), "f"(v.x), "f"(v.y), "f"(v.z), "f"(v.w) : "memory");
}
__device__ __forceinline__ void mbar_init(uint32_t a, uint32_t cnt) {
    asm volatile("mbarrier.init.shared.b64 [%0], %1;" :: "r"(a), "r"(cnt) : "memory");
}
__device__ __forceinline__ void mbar_arrive_cl(uint32_t ra) {
    asm volatile("mbarrier.arrive.release.cluster.shared::cluster.b64 _, [%0];" :: "r"(ra) : "memory");
}
__device__ __forceinline__ void fence_cl() {
    asm volatile("fence.acq_rel.cluster;" ::: "memory");
}
#define MBAR_WAIT_CL(addr, par) do { \
    uint32_t _d; \
    asm volatile("{\n\t.reg .pred p;\n\t" \
        "mbarrier.try_wait.parity.acquire.cluster.shared::cta.b64 p, [%1], %2;\n\t" \
        "selp.b32 %0, 1, 0, p;\n\t}" : "=r"(_d) : "r"(addr), "r"(par) : "memory"); \
    if (!_d) { \
        asm volatile("{\n\t.reg .pred P1;\n\t" \
            "W%=:\n\t" \
            "mbarrier.try_wait.parity.acquire.cluster.shared::cta.b64 P1, [%0], %1, 0x989680;\n\t" \
            "@P1 bra.uni D%=;\n\t" \
            "bra.uni W%=;\n\t" \
            "D%=:\n\t}" :: "r"(addr), "r"(par) : "memory"); \
    } \
} while (0)

#define CLUSTER_SYNC() do { \
    asm volatile("barrier.cluster.arrive.aligned;" ::: "memory"); \
    asm volatile("barrier.cluster.wait.aligned;"   ::: "memory"); } while (0)

// column-GEMV: Kq float4 k-steps, weights at float4-stride STRIDE
template<int Kq, int STRIDE, bool G>
__device__ __forceinline__ float colgemv(const float4* __restrict__ w4,
                                         const float4* __restrict__ in4) {
    float ax = 0.f, ay = 0.f, az = 0.f, aw = 0.f;
#pragma unroll
    for (int i = 0; i < Kq; i++) {
        float4 w = G ? __ldg(w4 + (size_t)i * STRIDE) : w4[(size_t)i * STRIDE];
        float4 x = in4[i];
        ax = fmaf(w.x, x.x, ax); ay = fmaf(w.y, x.y, ay);
        az = fmaf(w.z, x.z, az); aw = fmaf(w.w, x.w, aw);
    }
    return (ax + ay) + (az + aw);
}

template<int C, bool SW>
__device__ __forceinline__ void gc_body(
    const int* __restrict__ adj, const float* __restrict__ W,
    const float* __restrict__ a, const float* __restrict__ fc1w,
    const float* __restrict__ fc1b, const float* __restrict__ fc2w,
    const float* __restrict__ fc2b, const float* __restrict__ fc3w,
    const float* __restrict__ fc3b, const int* __restrict__ baseline,
    float* __restrict__ out, int out_size)
{
    constexpr int O1  = 512 / C;          // output cols per CTA (P1/z), 32 or 64
    constexpr int P   = TPB / O1;         // k-parts: 8 or 4
    constexpr int Kq  = 128 / P;          // float4 per part: 16 or 32
    constexpr int Ofr = H2D / C;          // fc2 cols per CTA: 25 or 50
    constexpr int O3r = (C == 16) ? 17 : 33;

    extern __shared__ __align__(16) unsigned char smem[];
    constexpr size_t SZ1 = SW ? (size_t)128 * O1  * 16 : 0;
    constexpr size_t SZ2 = SW ? (size_t)128 * Ofr * 16 : 0;
    constexpr size_t SZ3 = SW ? (size_t)128 * O3r * 16 : 0;
    float* TI1s = (float*)smem;
    float* TI2s = (float*)(smem + SZ1);
    float* TI3s = (float*)(smem + SZ1 + SZ2);
    unsigned char* fx = smem + SZ1 + SZ2 + SZ3;
    float*  sh_h    = (float*)(fx);            // 16*512
    float*  sh_ne   = (float*)(fx + 32768);    // 512
    float*  sh_a2   = (float*)(fx + 34816);    // 512
    float*  h1buf   = (float*)(fx + 36864);    // 512
    float*  h2p     = (float*)(fx + 38912);    // 512 (permuted h2, pads 0)
    float*  sh_part = (float*)(fx + 40960);    // 256
    float*  sh_ptz  = (float*)(fx + 41984);    // 256
    float4* tribuf  = (float4*)(fx + 43008);   // 16
    float*  sh_b1   = (float*)(fx + 43264);
    float*  sh_b2   = (float*)(fx + 43520);
    float*  sh_b3   = (float*)(fx + 43776);
    float*  sh_e    = (float*)(fx + 44032);    // 16
    float*  sh_loc  = (float*)(fx + 44096);    // 64
    float*  sh_red  = (float*)(fx + 44352);    // 16
    short*  colors16= (short*)(fx + 44416);    // 8192 shorts
    int*    sh_nbrc = (int*)(fx + 60800);      // 16
    int*    sh_misc = (int*)(fx + 60864);      // [0]=nused
    const uint32_t MB_H1  = s2u(fx + 60880);
    const uint32_t MB_H2  = s2u(fx + 60880) + 8;
    const uint32_t MB_TRI = s2u(fx + 60880) + 16;
    const uint32_t A_H1   = s2u(h1buf);
    const uint32_t A_H2P  = s2u(h2p);
    const uint32_t A_TRI  = s2u(tribuf);

    const int rank = blockIdx.x;
    const int tid  = threadIdx.x;
    const int warp = tid >> 5, lane = tid & 31;
    const int gtid = rank * TPB + tid;
    const int GS   = C * TPB;

    float lpp = 0.f, regv = 0.f;

    // ---------------- per-launch init ----------------
    if (tid == 0) {
        mbar_init(MB_H1, C); mbar_init(MB_H2, C); mbar_init(MB_TRI, C);
        sh_misc[0] = 1;
    }
    {
        float4 z4 = make_float4(0.f, 0.f, 0.f, 0.f);
        float4* zp = (float4*)g_z;
        const size_t nz4 = (size_t)NV * EMBD / 4;
        for (size_t i = gtid; i < nz4; i += GS) zp[i] = z4;
    }
    for (int d = gtid; d < 512 * 512; d += GS) {
        int c4 = d & 3, col = (d >> 2) & 511, kq = d >> 11;
        g_TIz[d] = W[(kq * 4 + c4) * 512 + col];
    }
    if (SW) {
        for (int d = tid; d < 128 * O1 * 4; d += TPB) {
            int c4 = d & 3, rest = d >> 2, jl = rest % O1, g = rest / O1, k = 4 * g + c4;
            TI1s[d] = fc1w[(rank * O1 + jl) * 512 + k];
        }
        for (int d = tid; d < 128 * Ofr * 4; d += TPB) {
            int c4 = d & 3, rest = d >> 2, jl = rest % Ofr, g = rest / Ofr, k = 4 * g + c4;
            TI2s[d] = fc2w[(rank * Ofr + jl) * 512 + k];
        }
        for (int d = tid; d < 128 * O3r * 4; d += TPB) {
            int c4 = d & 3, rest = d >> 2, jl = rest % O3r, g = rest / O3r, k = 4 * g + c4;
            int r2 = k / O1, is = k % O1, j3 = rank * O3r + jl;
            TI3s[d] = (is < Ofr && j3 < NL) ? fc3w[j3 * H2D + r2 * Ofr + is] : 0.f;
        }
    } else {
        for (int d = gtid; d < C * 128 * O1 * 4; d += GS) {
            int rk = d / (128 * O1 * 4), l = d % (128 * O1 * 4);
            int c4 = l & 3, rest = l >> 2, jl = rest % O1, g = rest / O1, k = 4 * g + c4;
            g_TI1g[d] = fc1w[(rk * O1 + jl) * 512 + k];
        }
        for (int d = gtid; d < C * 128 * Ofr * 4; d += GS) {
            int rk = d / (128 * Ofr * 4), l = d % (128 * Ofr * 4);
            int c4 = l & 3, rest = l >> 2, jl = rest % Ofr, g = rest / Ofr, k = 4 * g + c4;
            g_TI2g[d] = fc2w[(rk * Ofr + jl) * 512 + k];
        }
        for (int d = gtid; d < C * 128 * O3r * 4; d += GS) {
            int rk = d / (128 * O3r * 4), l = d % (128 * O3r * 4);
            int c4 = l & 3, rest = l >> 2, jl = rest % O3r, g = rest / O3r, k = 4 * g + c4;
            int r2 = k / O1, is = k % O1, j3 = rk * O3r + jl;
            g_TI3g[d] = (is < Ofr && j3 < NL) ? fc3w[j3 * H2D + r2 * Ofr + is] : 0.f;
        }
    }
    for (int i = tid; i < NV; i += TPB) colors16[i] = (i == 0) ? 0 : -1;
    for (int i = tid; i < EMBD; i += TPB) sh_a2[i] = a[EMBD + i];
    for (int i = tid; i < 512; i += TPB) h2p[i] = 0.f;
    if (tid < 64) sh_loc[tid] = -INFINITY;
    if (tid < O1)  sh_b1[tid] = fc1b[rank * O1 + tid];
    if (tid < Ofr) sh_b2[tid] = fc2b[rank * Ofr + tid];
    if (tid < O3r) { int j = rank * O3r + tid; sh_b3[tid] = (j < NL) ? fc3b[j] : 0.f; }

    // ---------------- Frobenius norms ----------------
    {
        float s[4] = {0.f, 0.f, 0.f, 0.f};
        for (int i = gtid; i < 768 * 512; i += GS) { float x = W[i];    s[0] += x * x; }
        for (int i = gtid; i < 512 * 512; i += GS) { float x = fc1w[i]; s[1] += x * x; }
        for (int i = gtid; i < 400 * 512; i += GS) { float x = fc2w[i]; s[2] += x * x; }
        for (int i = gtid; i < 257 * 400; i += GS) { float x = fc3w[i]; s[3] += x * x; }
#pragma unroll
        for (int m = 0; m < 4; m++) {
            float w = wsum(s[m]);
            __syncthreads();
            if (lane == 0) sh_red[warp] = w;
            __syncthreads();
            if (warp == 0) {
                float v2 = (lane < 8) ? sh_red[lane] : 0.f;
                v2 = wsum(v2);
                if (lane == 0) g_red[rank * 4 + m] = v2;
            }
            __syncthreads();
        }
    }
    CLUSTER_SYNC();   // init + weights + mbarriers + norms visible cluster-wide

    if (rank == 0 && tid == 0) {
        for (int m = 0; m < 4; m++) {
            float ssq = 0.f;
            for (int c = 0; c < C; c++) ssq += __ldcg(&g_red[c * 4 + m]);
            regv += sqrtf(ssq);
        }
    }

    // ---------------- prefetch state (2 rows per warp: t, t+8) ----------------
    float4 pz0[4], pw0[4], pz1[4], pw1[4];
    int nu0, nu1, pc0, pc1;

    auto pref_row = [&](int nu, int vexcl, int& pc, float4* pz, float4* pw) {
        if (nu == vexcl) { pc = DEFERC; return; }
        int c = (int)colors16[nu];
        pc = c;
        const float4* zp = (const float4*)(g_z + (size_t)nu * EMBD);
#pragma unroll
        for (int i = 0; i < 4; i++) pz[i] = __ldcg(zp + lane + 32 * i);
        if ((unsigned)c < NPCC) {
            const float4* wp = (const float4*)(W + (size_t)(EMBD + c) * EMBD);
#pragma unroll
            for (int i = 0; i < 4; i++) pw[i] = __ldg(wp + lane + 32 * i);
        } else {
#pragma unroll
            for (int i = 0; i < 4; i++) pw[i] = make_float4(0.f, 0.f, 0.f, 0.f);
        }
    };

    auto rowA = [&](int t, int nu, int pc, float4* pz, float4* pw) {
        int c = pc;
        if (c == DEFERC) {   // rare: neighbor == previous vertex
            c = (int)colors16[nu];
            const float4* zp = (const float4*)(g_z + (size_t)nu * EMBD);
#pragma unroll
            for (int i = 0; i < 4; i++) pz[i] = __ldcg(zp + lane + 32 * i);
            if ((unsigned)c < NPCC) {
                const float4* wp = (const float4*)(W + (size_t)(EMBD + c) * EMBD);
#pragma unroll
                for (int i = 0; i < 4; i++) pw[i] = __ldg(wp + lane + 32 * i);
            } else {
#pragma unroll
                for (int i = 0; i < 4; i++) pw[i] = make_float4(0.f, 0.f, 0.f, 0.f);
            }
        }
        if (lane == 0) sh_nbrc[t] = c;
        float4* hrow = (float4*)(sh_h + t * EMBD);
        const float4* a24 = (const float4*)sh_a2;
        float d2 = 0.f;
#pragma unroll
        for (int i = 0; i < 4; i++) {
            float4 hv;
            hv.x = pz[i].x + pw[i].x; hv.y = pz[i].y + pw[i].y;
            hv.z = pz[i].z + pw[i].z; hv.w = pz[i].w + pw[i].w;
            hrow[lane + 32 * i] = hv;
            d2 += dot4(hv, a24[lane + 32 * i]);
        }
        d2 = wsum(d2);
        if (lane == 0) sh_e[t] = d2;
    };

    nu0 = adj[DEG + warp];
    nu1 = adj[DEG + warp + 8];
    pref_row(nu0, -12345, pc0, pz0, pw0);
    pref_row(nu1, -12345, pc1, pz1, pw1);

    const float4* ne4 = (const float4*)sh_ne;

    // ======================= sequential scan =======================
    for (int v = 1; v < NV; ++v) {
        const int ph = (v & 1) ^ 1;
        int nnu0 = 0, nnu1 = 0;
        if (v + 1 < NV) {
            nnu0 = adj[(v + 1) * DEG + warp];
            nnu1 = adj[(v + 1) * DEG + warp + 8];
        }

        // ---- Stage A: rows from prefetched regs ----
        rowA(warp,     nu0, pc0, pz0, pw0);
        rowA(warp + 8, nu1, pc1, pz1, pw1);
        __syncthreads();   // bar1

        // ---- softmax (replicated per warp) + new_e ----
        {
            float ev;
            if (lane == 0) ev = 0.f;
            else if (lane < 17) { float t = sh_e[lane - 1]; ev = (t > 0.f) ? t : 0.2f * t; }
            else ev = -INFINITY;
            float m = ev;
#pragma unroll
            for (int o = 16; o; o >>= 1) m = fmaxf(m, __shfl_xor_sync(0xffffffffu, m, o));
            float p = (lane < 17) ? expf(ev - m) : 0.f;
            float s = wsum(p);
            float attn = p / s;
#pragma unroll
            for (int jj = 0; jj < 2; jj++) {
                int j = tid + jj * 256;
                float acc = 0.f;
#pragma unroll
                for (int t = 1; t < 17; t++)
                    acc += __shfl_sync(0xffffffffu, attn, t) * sh_h[(t - 1) * EMBD + j];
                sh_ne[j] = (acc > 0.f) ? acc : expm1f(acc);
            }
        }
        __syncthreads();   // bar2

        // ---- P1: fc1 partials (SMEM weights) ----
        {
            int p = tid / O1, jl = tid % O1;
            const float4* w4 = SW ? (const float4*)TI1s + (size_t)(p * Kq) * O1 + jl
                                  : (const float4*)g_TI1g + (size_t)rank * (128 * O1)
                                        + (size_t)(p * Kq) * O1 + jl;
            sh_part[tid] = colgemv<Kq, O1, !SW>(w4, ne4 + p * Kq);
        }
        __syncthreads();   // bar3

        if (tid < O1) {
            float sum = 0.f;
#pragma unroll
            for (int q = 0; q < P; q++) sum += sh_part[q * O1 + tid];
            float h = sum + sh_b1[tid];
            h = (h > 0.f) ? h : 0.01f * h;
            uint32_t off = A_H1 + (rank * O1 + tid) * 4;
#pragma unroll
            for (int c = 0; c < C; c++) sts_cl_f32(mapa_u32(off, c), h);
        }
        {   // z partials (overlapped; weights L1-resident via ldg)
            int p = tid / O1, jl = tid % O1;
            const float4* w4 = (const float4*)g_TIz + (size_t)(p * Kq) * 512 + rank * O1 + jl;
            sh_ptz[tid] = colgemv<Kq, 512, true>(w4, ne4 + p * Kq);
        }
        __syncthreads();   // bar4

        if (warp == 0 && lane < C) { fence_cl(); mbar_arrive_cl(mapa_u32(MB_H1, lane)); }
        {
            int zt = tid - O1;
            if (zt >= 0 && zt < O1) {
                float sum = 0.f;
#pragma unroll
                for (int q = 0; q < P; q++) sum += sh_ptz[q * O1 + zt];
                __stcg(&g_z[(size_t)v * EMBD + rank * O1 + zt], sum);
            }
        }
        MBAR_WAIT_CL(MB_H1, ph);

        // ---- P2: fc2 partials over full h1 (local SMEM) ----
        {
            int p = tid / O1, jl = tid % O1;
            if (jl < Ofr) {
                const float4* w4 = SW ? (const float4*)TI2s + (size_t)(p * Kq) * Ofr + jl
                                      : (const float4*)g_TI2g + (size_t)rank * (128 * Ofr)
                                            + (size_t)(p * Kq) * Ofr + jl;
                sh_part[tid] = colgemv<Kq, Ofr, !SW>(w4, (const float4*)h1buf + p * Kq);
            }
        }
        __syncthreads();   // bar5

        if (tid < Ofr) {
            float sum = 0.f;
#pragma unroll
            for (int q = 0; q < P; q++) sum += sh_part[q * O1 + tid];
            float h = sum + sh_b2[tid];
            h = (h > 0.f) ? h : 0.01f * h;
            uint32_t off = A_H2P + (rank * O1 + tid) * 4;
#pragma unroll
            for (int c = 0; c < C; c++) sts_cl_f32(mapa_u32(off, c), h);
        }
        __syncthreads();   // bar5b

        if (warp == 0 && lane < C) { fence_cl(); mbar_arrive_cl(mapa_u32(MB_H2, lane)); }
        if (v + 1 < NV) {   // prefetch next step's rows during the wait window
            pref_row(nnu0, v, pc0, pz0, pw0);
            pref_row(nnu1, v, pc1, pz1, pw1);
            nu0 = nnu0; nu1 = nnu1;
        }
        MBAR_WAIT_CL(MB_H2, ph);

        // ---- P3: fc3 partials over permuted h2 (local SMEM) ----
        {
            int p = tid / O1, jl = tid % O1;
            if (jl < O3r) {
                const float4* w4 = SW ? (const float4*)TI3s + (size_t)(p * Kq) * O3r + jl
                                      : (const float4*)g_TI3g + (size_t)rank * (128 * O3r)
                                            + (size_t)(p * Kq) * O3r + jl;
                sh_part[tid] = colgemv<Kq, O3r, !SW>(w4, (const float4*)h2p + p * Kq);
            }
        }
        __syncthreads();   // bar6

        if (tid < O1) {
            float mlv = -INFINITY;
            if (tid < O3r) {
                int j = rank * O3r + tid;
                if (j < NL) {
                    float sum = 0.f;
#pragma unroll
                    for (int q = 0; q < P; q++) sum += sh_part[q * O1 + tid];
                    float L = sum + sh_b3[tid];
                    int nused = sh_misc[0];
                    bool irrel = (j >= nused) && (j < NPCC);
                    bool am = false;
#pragma unroll
                    for (int t = 0; t < 16; t++) am |= (sh_nbrc[t] == j);
                    mlv = (irrel || am) ? -INFINITY : L;
                }
            }
            sh_loc[tid] = mlv;
        }
        __syncthreads();   // bar6b

        if (warp == 0) {
            float v1 = sh_loc[lane];      int i1 = lane;
            float v2 = sh_loc[lane + 32]; int i2 = lane + 32;
            if (v2 > v1) { v1 = v2; i1 = i2; }
            float rv = v1; int ri = i1;
#pragma unroll
            for (int o = 16; o; o >>= 1) {
                float ov = __shfl_xor_sync(0xffffffffu, rv, o);
                int   oi = __shfl_xor_sync(0xffffffffu, ri, o);
                if (ov > rv || (ov == rv && oi < ri)) { rv = ov; ri = oi; }
            }
            float t0 = (sh_loc[lane]      == -INFINITY) ? 0.f : expf(sh_loc[lane]      - rv);
            float t1 = (sh_loc[lane + 32] == -INFINITY) ? 0.f : expf(sh_loc[lane + 32] - rv);
            float lsum = wsum(t0 + t1);
            if (rv == -INFINITY) lsum = 0.f;
            if (lane < C) {
                fence_cl();   // releases prior g_z stores too (bar-chain)
                float4 tri = make_float4(rv, lsum, __int_as_float(rank * O3r + ri), 0.f);
                sts_cl_f4(mapa_u32(A_TRI + rank * 16, lane), tri);
                mbar_arrive_cl(mapa_u32(MB_TRI, lane));
            }
        }
        MBAR_WAIT_CL(MB_TRI, ph);

        // ---- E: combine (replicated), commit ----
        if (warp == 0) {
            float cv = -INFINITY, cs = 0.f; int ci = 0x7fffffff;
            if (lane < C) {
                float4 t4 = tribuf[lane];
                cv = t4.x; cs = t4.y; ci = __float_as_int(t4.z);
            }
            float mv = cv; int mi = ci;
#pragma unroll
            for (int o = 16; o; o >>= 1) {
                float ov = __shfl_xor_sync(0xffffffffu, mv, o);
                int   oi = __shfl_xor_sync(0xffffffffu, mi, o);
                if (ov > mv || (ov == mv && oi < mi)) { mv = ov; mi = oi; }
            }
            float term = (lane < C && cv != -INFINITY) ? cs * expf(cv - mv) : 0.f;
            float gsum = wsum(term);
            if (lane == 0) {
                int cur    = sh_misc[0];
                int isnew  = (mi == NPCC) ? 1 : 0;
                colors16[v] = (short)(isnew ? cur : mi);
                sh_misc[0] = cur + isnew;
                lpp += logf(1.f / gsum + 1e-8f) + 18.420680743952367f;
            }
        }
        __syncthreads();   // bar7
    }

    // ---------------- output: [colors..., loss] ----------------
    for (int i = gtid; i < NV && i < out_size; i += GS)
        out[i] = (float)colors16[i];
    if (rank == 0 && tid == 0 && out_size > NV) {
        float loss = ((float)sh_misc[0] - (float)baseline[0]) * lpp / (float)NV + 0.05f * regv;
        out[NV] = loss;
    }
}

#define PARAMS const int* adj, const float* W, const float* a, const float* fc1w, \
               const float* fc1b, const float* fc2w, const float* fc2b,           \
               const float* fc3w, const float* fc3b, const int* baseline,         \
               float* out, int out_size
#define ARGS adj, W, a, fc1w, fc1b, fc2w, fc2b, fc3w, fc3b, baseline, out, out_size

__global__ void __launch_bounds__(TPB, 1)
gc_k16(PARAMS) { gc_body<16, true>(ARGS); }

__global__ void __launch_bounds__(TPB, 1) __cluster_dims__(8, 1, 1)
gc_k8(PARAMS) { gc_body<8, false>(ARGS); }

#define SMEM16 212480   // 60912 fixed + 151552 smem-weight slices
#define SMEM8  61440

extern "C" void kernel_launch(void* const* d_in, const int* in_sizes, int n_in,
                              void* d_out, int out_size) {
    (void)in_sizes; (void)n_in;
    const int*   adj  = (const int*)d_in[0];
    const float* W    = (const float*)d_in[1];
    const float* a    = (const float*)d_in[2];
    const float* fc1w = (const float*)d_in[3];
    const float* fc1b = (const float*)d_in[4];
    const float* fc2w = (const float*)d_in[5];
    const float* fc2b = (const float*)d_in[6];
    const float* fc3w = (const float*)d_in[7];
    const float* fc3b = (const float*)d_in[8];
    const int*   bl   = (const int*)d_in[9];
    float* out = (float*)d_out;

    cudaFuncSetAttribute(gc_k16, cudaFuncAttributeNonPortableClusterSizeAllowed, 1);
    cudaFuncSetAttribute(gc_k16, cudaFuncAttributeMaxDynamicSharedMemorySize, SMEM16);
    cudaFuncSetAttribute(gc_k8,  cudaFuncAttributeMaxDynamicSharedMemorySize, SMEM8);
    (void)cudaGetLastError();

    int maxC = 0;
    cudaLaunchConfig_t q = {};
    q.gridDim = {16, 1, 1}; q.blockDim = {TPB, 1, 1};
    q.dynamicSmemBytes = SMEM16; q.stream = 0;
    cudaError_t qe = cudaOccupancyMaxPotentialClusterSize(&maxC, gc_k16, &q);
    (void)cudaGetLastError();

    if (qe == cudaSuccess && maxC >= 16) {
        cudaLaunchConfig_t cfg = {};
        cfg.gridDim = {16, 1, 1}; cfg.blockDim = {TPB, 1, 1};
        cfg.dynamicSmemBytes = SMEM16; cfg.stream = 0;
        cudaLaunchAttribute at[1];
        at[0].id = cudaLaunchAttributeClusterDimension;
        at[0].val.clusterDim = {16, 1, 1};
        cfg.attrs = at; cfg.numAttrs = 1;
        cudaLaunchKernelEx(&cfg, gc_k16, adj, W, a, fc1w, fc1b, fc2w, fc2b,
                           fc3w, fc3b, bl, out, out_size);
    } else {
        gc_k8<<<8, TPB, SMEM8>>>(adj, W, a, fc1w, fc1b, fc2w, fc2b,
                                 fc3w, fc3b, bl, out, out_size);
    }
}

// round 8
// speedup vs baseline: 3.5443x; 3.4063x over previous
#include <cuda_runtime.h>
#include <math.h>
#include <stdint.h>

#define NV   8192
#define DEG  16
#define NPCC 256
#define NL   257
#define G    48
#define TPB  512
#define NINF (-INFINITY)

// ---------------- persistent device scratch ----------------
__device__ __align__(16) float g_z[(size_t)NV * 512];   // z[u] = emb[u] @ W[:512]
__device__ __align__(16) float g_T1[512 * 512];         // T1[k*512+j] = fc1w[j][k]
__device__ __align__(16) float g_T2[512 * 512];         // T2[k*512+j] = fc2w[j][k], j-pad 0
__device__ __align__(16) float g_T3[400 * 512];         // T3[k*512+j] = fc3w[j][k], j-pad 0
__device__ int   g_colors[NV];
__device__ int   g_progress;     // highest committed vertex (release/acquire)
__device__ int   g_nused;
__device__ float g_lpp;
__device__ float g_regv;

// ---------------- smem layout (float indices) ----------------
#define S_H    0        // 8192  gathered h rows (16x512)
#define S_NE   8192     // 512
#define S_H1   8704     // 512
#define S_H2   9216     // 512 (pads stay 0)
#define S_A2   9728     // 512
#define S_B1   10240    // 512
#define S_B2   10752    // 512 (pads 0)
#define S_B3   11264    // 512 (pads 0)
#define S_P1   11776    // 2048 partials
#define S_PZ   13824    // 2048 partials (z)
#define S_E    15872    // 16
#define S_RED  15888    // 16
#define S_REDI 15904    // 16 (int)
#define S_NBR  15920    // 16 (int)
#define S_NBRC 15936    // 16 (int)
#define S_MISC 15952    // 8 (mixed)
#define S_TOT  15960
#define SMEMB  (S_TOT * 4)

__device__ __forceinline__ float wsum(float v) {
#pragma unroll
    for (int o = 16; o; o >>= 1) v += __shfl_xor_sync(0xffffffffu, v, o);
    return v;
}
__device__ __forceinline__ float dot4(float4 a, float4 b) {
    return a.x * b.x + a.y * b.y + a.z * b.z + a.w * b.w;
}
__device__ __forceinline__ int ld_acq(const int* p) {
    int v;
    asm volatile("ld.acquire.gpu.b32 %0, [%1];" : "=r"(v) : "l"(p) : "memory");
    return v;
}
__device__ __forceinline__ void st_rel(int* p, int v) {
    asm volatile("st.release.gpu.b32 [%0], %1;" :: "l"(p), "r"(v) : "memory");
}

// ---------------- init kernel: transposes + state reset (every launch) ----------------
__global__ void initk(const float* __restrict__ fc1w, const float* __restrict__ fc2w,
                      const float* __restrict__ fc3w) {
    int gt = blockIdx.x * blockDim.x + threadIdx.x;
    int GS = gridDim.x * blockDim.x;
    for (int d = gt; d < 512 * 512; d += GS) {
        int k = d >> 9, j = d & 511;
        g_T1[d] = fc1w[j * 512 + k];
        g_T2[d] = (j < 400) ? fc2w[j * 512 + k] : 0.f;
    }
    for (int d = gt; d < 400 * 512; d += GS) {
        int k = d >> 9, j = d & 511;
        g_T3[d] = (j < NL) ? fc3w[j * 400 + k] : 0.f;
    }
    for (int i = gt; i < NV; i += GS) g_colors[i] = (i == 0) ? 0 : -1;
    for (int i = gt; i < 512; i += GS) g_z[i] = 0.f;     // only row 0 ever read un-written
    if (gt == 0) { g_progress = 0; g_nused = 1; g_lpp = 0.f; g_regv = 0.f; }
}

// column-GEMV partial: 4 outputs (j4) over k-range [kp*KQ, kp*KQ+KQ)
template<int KQ>
__device__ __forceinline__ void gpart(const float* __restrict__ Tg,
                                      const float* __restrict__ xin,
                                      float* __restrict__ psh, int j4, int kp) {
    const float4* w = (const float4*)Tg + (size_t)(kp * KQ) * 128 + j4;
    const float*  x = xin + kp * KQ;
    float ax = 0.f, ay = 0.f, az = 0.f, aw = 0.f;
#pragma unroll 4
    for (int k = 0; k < KQ; k++) {
        float xv = x[k];
        float4 ww = __ldg(w); w += 128;
        ax = fmaf(ww.x, xv, ax); ay = fmaf(ww.y, xv, ay);
        az = fmaf(ww.z, xv, az); aw = fmaf(ww.w, xv, aw);
    }
    ((float4*)(psh + kp * 512))[j4] = make_float4(ax, ay, az, aw);
}

__global__ void __launch_bounds__(TPB, 1)
gc_main(const int* __restrict__ adj, const float* __restrict__ W,
        const float* __restrict__ a, const float* __restrict__ fc1w,
        const float* __restrict__ fc1b, const float* __restrict__ fc2w,
        const float* __restrict__ fc2b, const float* __restrict__ fc3w,
        const float* __restrict__ fc3b, const int* __restrict__ baseline,
        float* __restrict__ out, int out_size)
{
    extern __shared__ __align__(16) float sm[];
    int*   smi     = (int*)sm;
    float* sh_h    = sm + S_H;
    float* sh_ne   = sm + S_NE;
    float* sh_h1   = sm + S_H1;
    float* sh_h2   = sm + S_H2;
    float* sh_a2   = sm + S_A2;
    float* sh_b1   = sm + S_B1;
    float* sh_b2   = sm + S_B2;
    float* sh_b3   = sm + S_B3;
    float* sh_p1   = sm + S_P1;
    float* sh_pz   = sm + S_PZ;
    float* sh_e    = sm + S_E;
    float* sh_red  = sm + S_RED;
    int*   sh_redi = smi + S_REDI;
    int*   sh_nbr  = smi + S_NBR;
    int*   sh_nbrc = smi + S_NBRC;
    int*   sh_mi   = smi + S_MISC;
    float* sh_mf   = sm + S_MISC;

    const int rank = blockIdx.x;
    const int tid  = threadIdx.x;
    const int warp = tid >> 5, lane = tid & 31;
    const int j4 = tid & 127, kp = tid >> 7;

    // per-CTA constants
    sh_a2[tid] = a[512 + tid];
    sh_b1[tid] = fc1b[tid];
    sh_b2[tid] = (tid < 400) ? fc2b[tid] : 0.f;
    sh_b3[tid] = (tid < NL)  ? fc3b[tid] : 0.f;
    for (int i = tid; i < 512; i += TPB) sh_h2[i] = 0.f;
    __syncthreads();

    // ---------------- rank 0: Frobenius norms (before its first commit) ----------------
    if (rank == 0) {
        float s[4] = {0.f, 0.f, 0.f, 0.f};
        for (int i = tid; i < 768 * 512; i += TPB) { float x = W[i];    s[0] += x * x; }
        for (int i = tid; i < 512 * 512; i += TPB) { float x = fc1w[i]; s[1] += x * x; }
        for (int i = tid; i < 400 * 512; i += TPB) { float x = fc2w[i]; s[2] += x * x; }
        for (int i = tid; i < 257 * 400; i += TPB) { float x = fc3w[i]; s[3] += x * x; }
        float regv = 0.f;
#pragma unroll
        for (int m = 0; m < 4; m++) {
            float w = wsum(s[m]);
            __syncthreads();
            if (lane == 0) sh_red[warp] = w;
            __syncthreads();
            if (warp == 0) {
                float v2 = (lane < 16) ? sh_red[lane] : 0.f;
                v2 = wsum(v2);
                if (lane == 0) sh_mf[4] = sqrtf(v2);
            }
            __syncthreads();
            regv += sh_mf[4];
            __syncthreads();
        }
        if (tid == 0) {
            g_regv = regv;                       // ordered by commit(1)'s release
            if (out_size > 0) out[0] = 0.f;
        }
    }

    int cache = 0;   // tid0-private: highest progress this CTA has acquired

    // ======================= pipelined speculative scan =======================
    for (int v = 1 + rank; v < NV; v += G) {
        if (tid < 16) sh_nbr[tid] = adj[v * DEG + tid];
        __syncthreads();

        // ---- gate: wait for latest in-window neighbor to commit ----
        if (tid == 0) {
            int maxu = -1;
#pragma unroll
            for (int t = 0; t < 16; t++) { int u = sh_nbr[t]; if (u < v && u > maxu) maxu = u; }
            if (maxu > cache) {
                int p;
                do { p = ld_acq(&g_progress); } while (p < maxu);
                cache = p;
            }
        }
        __syncthreads();

        // ---- Stage A: 16 neighbor rows, one per warp (h_self == 0) ----
        {
            int u = sh_nbr[warp];
            float d2 = 0.f;
            int c = -1;
            float4* hrow = (float4*)(sh_h + warp * 512);
            const float4* a24 = (const float4*)sh_a2;
            if (u >= v) {
                float4 zr = make_float4(0.f, 0.f, 0.f, 0.f);
#pragma unroll
                for (int i = 0; i < 4; i++) hrow[lane + 32 * i] = zr;
            } else {
                c = __ldcg(&g_colors[u]);       // committed => final, >= 0
                const float4* zp = (const float4*)(g_z + (size_t)u * 512);
                const float4* wp = ((unsigned)c < NPCC)
                                 ? (const float4*)(W + (size_t)(512 + c) * 512) : (const float4*)0;
#pragma unroll
                for (int i = 0; i < 4; i++) {
                    float4 hv = __ldcg(zp + lane + 32 * i);
                    if (wp) { float4 wv = __ldg(wp + lane + 32 * i);
                              hv.x += wv.x; hv.y += wv.y; hv.z += wv.z; hv.w += wv.w; }
                    hrow[lane + 32 * i] = hv;
                    d2 += dot4(hv, a24[lane + 32 * i]);
                }
                d2 = wsum(d2);
            }
            if (lane == 0) { sh_e[warp] = d2; sh_nbrc[warp] = c; }
        }
        __syncthreads();

        // ---- softmax (replicated per warp) + new_e = elu(attn @ h) ----
        {
            float ev;
            if (lane == 0) ev = 0.f;                         // self row: e = leaky(0) = 0
            else if (lane < 17) { float t = sh_e[lane - 1]; ev = (t > 0.f) ? t : 0.2f * t; }
            else ev = NINF;
            float m = ev;
#pragma unroll
            for (int o = 16; o; o >>= 1) m = fmaxf(m, __shfl_xor_sync(0xffffffffu, m, o));
            float p = (lane < 17) ? expf(ev - m) : 0.f;
            float s = wsum(p);
            float attn = p / s;
            float acc = 0.f;
#pragma unroll
            for (int t = 1; t < 17; t++)
                acc += __shfl_sync(0xffffffffu, attn, t) * sh_h[(t - 1) * 512 + tid];
            sh_ne[tid] = (acc > 0.f) ? acc : expm1f(acc);
        }
        __syncthreads();

        // ---- P1 (fc1) + z partials ----
        gpart<128>(g_T1, sh_ne, sh_p1, j4, kp);
        gpart<128>(W,    sh_ne, sh_pz, j4, kp);
        __syncthreads();
        {
            float s1 = sh_p1[tid] + sh_p1[512 + tid] + sh_p1[1024 + tid] + sh_p1[1536 + tid];
            float h = s1 + sh_b1[tid];
            sh_h1[tid] = (h > 0.f) ? h : 0.01f * h;
            float sz = sh_pz[tid] + sh_pz[512 + tid] + sh_pz[1024 + tid] + sh_pz[1536 + tid];
            __stcg(&g_z[(size_t)v * 512 + tid], sz);
        }
        __syncthreads();

        // ---- P2 (fc2) ----
        gpart<128>(g_T2, sh_h1, sh_p1, j4, kp);
        __syncthreads();
        {
            float s1 = sh_p1[tid] + sh_p1[512 + tid] + sh_p1[1024 + tid] + sh_p1[1536 + tid];
            float h = s1 + sh_b2[tid];                       // pads: 0 weights + 0 bias -> 0
            sh_h2[tid] = (h > 0.f) ? h : 0.01f * h;
        }
        __syncthreads();

        // ---- P3 (fc3) -> logits in registers ----
        gpart<100>(g_T3, sh_h2, sh_p1, j4, kp);
        __syncthreads();
        float L = NINF;
        if (tid < NL)
            L = sh_p1[tid] + sh_p1[512 + tid] + sh_p1[1024 + tid] + sh_p1[1536 + tid]
              + sh_b3[tid];
        __syncthreads();

        // ---- commit: acquire chain, mask, argmax, publish ----
        float lpp0;
        if (tid == 0) {
            int p;
            do { p = ld_acq(&g_progress); } while (p < v - 1);
            cache = p;
            sh_mi[0] = __ldcg(&g_nused);
            lpp0 = __ldcg(&g_lpp);
        }
        __syncthreads();

        float mlv = L;
        if (tid < NL) {
            int nused = sh_mi[0];
            bool irrel = (tid >= nused) && (tid < NPCC);
            bool am = false;
#pragma unroll
            for (int t = 0; t < 16; t++) am |= (sh_nbrc[t] == tid);
            if (irrel || am) mlv = NINF;
        }
        {
            float rv = mlv; int ri = tid;
#pragma unroll
            for (int o = 16; o; o >>= 1) {
                float ov = __shfl_xor_sync(0xffffffffu, rv, o);
                int   oi = __shfl_xor_sync(0xffffffffu, ri, o);
                if (ov > rv || (ov == rv && oi < ri)) { rv = ov; ri = oi; }
            }
            if (lane == 0) { sh_red[warp] = rv; sh_redi[warp] = ri; }
        }
        __syncthreads();
        if (warp == 0) {
            float v2 = (lane < 16) ? sh_red[lane] : NINF;
            int   i2 = (lane < 16) ? sh_redi[lane] : 0x7fffffff;
#pragma unroll
            for (int o = 16; o; o >>= 1) {
                float ov = __shfl_xor_sync(0xffffffffu, v2, o);
                int   oi = __shfl_xor_sync(0xffffffffu, i2, o);
                if (ov > v2 || (ov == v2 && oi < i2)) { v2 = ov; i2 = oi; }
            }
            if (lane == 0) { sh_mi[2] = i2; sh_mf[3] = v2; }
        }
        __syncthreads();
        {
            float gmax = sh_mf[3];
            float pe = (mlv == NINF) ? 0.f : expf(mlv - gmax);
            pe = wsum(pe);
            if (lane == 0) sh_red[warp] = pe;
        }
        __syncthreads();
        if (tid == 0) {
            float gsum = 0.f;
            for (int w = 0; w < 16; w++) gsum += sh_red[w];
            int mi     = sh_mi[2];
            int cur    = sh_mi[0];
            int isnew  = (mi == NPCC) ? 1 : 0;
            int chosen = isnew ? cur : mi;
            int nn     = cur + isnew;
            float lppn = lpp0 + logf(1.f / gsum + 1e-8f) + 18.420680743952367f;
            g_colors[v] = chosen;
            g_nused = nn;
            g_lpp = lppn;
            if (v < out_size) out[v] = (float)chosen;
            if (v == NV - 1 && out_size > NV) {
                float loss = ((float)nn - (float)baseline[0]) * lppn / (float)NV
                           + 0.05f * __ldcg(&g_regv);
                out[NV] = loss;
            }
            st_rel(&g_progress, v);
            cache = v;
        }
        __syncthreads();
    }
}

extern "C" void kernel_launch(void* const* d_in, const int* in_sizes, int n_in,
                              void* d_out, int out_size) {
    (void)in_sizes; (void)n_in;
    const int*   adj  = (const int*)d_in[0];
    const float* W    = (const float*)d_in[1];
    const float* a    = (const float*)d_in[2];
    const float* fc1w = (const float*)d_in[3];
    const float* fc1b = (const float*)d_in[4];
    const float* fc2w = (const float*)d_in[5];
    const float* fc2b = (const float*)d_in[6];
    const float* fc3w = (const float*)d_in[7];
    const float* fc3b = (const float*)d_in[8];
    const int*   bl   = (const int*)d_in[9];
    float* out = (float*)d_out;

    static int smem_set = 0;
    if (!smem_set) {
        cudaFuncSetAttribute(gc_main, cudaFuncAttributeMaxDynamicSharedMemorySize, SMEMB);
        smem_set = 1;
    }
    initk<<<128, 256>>>(fc1w, fc2w, fc3w);
    gc_main<<<G, TPB, SMEMB>>>(adj, W, a, fc1w, fc1b, fc2w, fc2b,
                               fc3w, fc3b, bl, out, out_size);
}

// round 9
// speedup vs baseline: 5.3790x; 1.5177x over previous
#include <cuda_runtime.h>
#include <math.h>
#include <stdint.h>

#define NV   8192
#define DEG  16
#define NPCC 256
#define NL   257
#define G    64
#define TPB  1024
#define NINF (-INFINITY)
#define FINAL_RANK ((NV - 2) % G)

// ---------------- persistent device scratch ----------------
__device__ __align__(16) float g_z[(size_t)NV * 512];
__device__ __align__(16) float g_T1[512 * 512];   // T1[k*512+j] = fc1w[j][k]
__device__ __align__(16) float g_T2[512 * 512];   // T2[k*512+j] = fc2w[j][k], j-pad 0
__device__ __align__(16) float g_T3[400 * 512];   // T3[k*512+j] = fc3w[j][k], j-pad 0
__device__ int   g_colors[NV];
__device__ int   g_pp;              // packed (progress << 9) | nused   (release/acquire)
__device__ float g_regv;
__device__ float g_lppp[G];
__device__ int   g_done[G];

// ---------------- smem layout (float indices) ----------------
#define S_H    0        // 8192
#define S_P1   8192     // 4096
#define S_PZ   12288    // 4096
#define S_NE   16384    // 512
#define S_H1   16896    // 512
#define S_H2   17408    // 512
#define S_A2   17920    // 512
#define S_B1   18432    // 512
#define S_B2   18944    // 512
#define S_B3   19456    // 512
#define S_E2   19968    // 32
#define S_RED  20000    // 32
#define S_SUM  20032    // 32
#define S_REDI 20064    // 32 int
#define S_NBR  20096    // 16 int
#define S_NBRC 20112    // 16 int
#define S_MI   20128    // 8 int
#define S_GM   20136    // 1 float
#define S_TOT  20144
#define SMEMB  (S_TOT * 4)

__device__ __forceinline__ float wsum(float v) {
#pragma unroll
    for (int o = 16; o; o >>= 1) v += __shfl_xor_sync(0xffffffffu, v, o);
    return v;
}
__device__ __forceinline__ float dot4(float4 a, float4 b) {
    return a.x * b.x + a.y * b.y + a.z * b.z + a.w * b.w;
}
__device__ __forceinline__ int ld_acq(const int* p) {
    int v;
    asm volatile("ld.acquire.gpu.b32 %0, [%1];" : "=r"(v) : "l"(p) : "memory");
    return v;
}
__device__ __forceinline__ void st_rel(int* p, int v) {
    asm volatile("st.release.gpu.b32 [%0], %1;" :: "l"(p), "r"(v) : "memory");
}

// ---------------- init kernel (runs every launch) ----------------
__global__ void initk(const float* __restrict__ fc1w, const float* __restrict__ fc2w,
                      const float* __restrict__ fc3w) {
    int gt = blockIdx.x * blockDim.x + threadIdx.x;
    int GS = gridDim.x * blockDim.x;
    for (int d = gt; d < 512 * 512; d += GS) {
        int k = d >> 9, j = d & 511;
        g_T1[d] = fc1w[j * 512 + k];
        g_T2[d] = (j < 400) ? fc2w[j * 512 + k] : 0.f;
    }
    for (int d = gt; d < 400 * 512; d += GS) {
        int k = d >> 9, j = d & 511;
        g_T3[d] = (j < NL) ? fc3w[j * 400 + k] : 0.f;
    }
    for (int i = gt; i < NV; i += GS) g_colors[i] = (i == 0) ? 0 : -1;
    for (int i = gt; i < 512; i += GS) g_z[i] = 0.f;
    if (gt < G) { g_done[gt] = 0; g_lppp[gt] = 0.f; }
    if (gt == 0) { g_pp = 1; g_regv = 0.f; }    // progress=0, nused=1
}

// column-GEMV partial: KQ k-steps (even), weights pre-offset, stride 128 float4
template<int KQ>
__device__ __forceinline__ float4 gemv_part(const float4* __restrict__ w,
                                            const float* __restrict__ x) {
    float4 e = make_float4(0.f, 0.f, 0.f, 0.f);
    float4 o = make_float4(0.f, 0.f, 0.f, 0.f);
#pragma unroll 8
    for (int k = 0; k < KQ; k += 2) {
        float x0 = x[k], x1 = x[k + 1];
        float4 w0 = __ldcg(w + (size_t)k * 128);
        float4 w1 = __ldcg(w + (size_t)(k + 1) * 128);
        e.x = fmaf(w0.x, x0, e.x); e.y = fmaf(w0.y, x0, e.y);
        e.z = fmaf(w0.z, x0, e.z); e.w = fmaf(w0.w, x0, e.w);
        o.x = fmaf(w1.x, x1, o.x); o.y = fmaf(w1.y, x1, o.y);
        o.z = fmaf(w1.z, x1, o.z); o.w = fmaf(w1.w, x1, o.w);
    }
    return make_float4(e.x + o.x, e.y + o.y, e.z + o.z, e.w + o.w);
}

__global__ void __launch_bounds__(TPB, 1)
gc_main(const int* __restrict__ adj, const float* __restrict__ W,
        const float* __restrict__ a, const float* __restrict__ fc1w,
        const float* __restrict__ fc1b, const float* __restrict__ fc2w,
        const float* __restrict__ fc2b, const float* __restrict__ fc3w,
        const float* __restrict__ fc3b, const int* __restrict__ baseline,
        float* __restrict__ out, int out_size)
{
    extern __shared__ __align__(16) float sm[];
    int*   smi     = (int*)sm;
    float* sh_h    = sm + S_H;
    float* sh_p1   = sm + S_P1;
    float* sh_pz   = sm + S_PZ;
    float* sh_ne   = sm + S_NE;
    float* sh_h1   = sm + S_H1;
    float* sh_h2   = sm + S_H2;
    float* sh_a2   = sm + S_A2;
    float* sh_b1   = sm + S_B1;
    float* sh_b2   = sm + S_B2;
    float* sh_b3   = sm + S_B3;
    float* sh_e2   = sm + S_E2;
    float* sh_red  = sm + S_RED;
    float* sh_sum  = sm + S_SUM;
    int*   sh_redi = smi + S_REDI;
    int*   sh_nbr  = smi + S_NBR;
    int*   sh_nbrc = smi + S_NBRC;
    int*   sh_mi   = smi + S_MI;
    float* sh_gm   = sm + S_GM;

    const int rank = blockIdx.x;
    const int tid  = threadIdx.x;
    const int warp = tid >> 5, lane = tid & 31;
    const int j4 = tid & 127, kp = tid >> 7;     // 128 j4-groups x 8 k-parts

    float lpp = 0.f;
    int last_nn = 0;

    // per-CTA constants
    if (tid < 512) {
        sh_a2[tid] = a[512 + tid];
        sh_b1[tid] = fc1b[tid];
        sh_b2[tid] = (tid < 400) ? fc2b[tid] : 0.f;
        sh_b3[tid] = (tid < NL)  ? fc3b[tid] : 0.f;
    }
    __syncthreads();

    // rank 0: Frobenius norms before its first commit
    if (rank == 0) {
        float s[4] = {0.f, 0.f, 0.f, 0.f};
        for (int i = tid; i < 768 * 512; i += TPB) { float x = W[i];    s[0] += x * x; }
        for (int i = tid; i < 512 * 512; i += TPB) { float x = fc1w[i]; s[1] += x * x; }
        for (int i = tid; i < 400 * 512; i += TPB) { float x = fc2w[i]; s[2] += x * x; }
        for (int i = tid; i < 257 * 400; i += TPB) { float x = fc3w[i]; s[3] += x * x; }
        float regv = 0.f;
#pragma unroll
        for (int m = 0; m < 4; m++) {
            float w = wsum(s[m]);
            __syncthreads();
            if (lane == 0) sh_red[warp] = w;
            __syncthreads();
            if (warp == 0) {
                float v2 = sh_red[lane];
                v2 = wsum(v2);
                if (lane == 0) sh_gm[0] = sqrtf(v2);
            }
            __syncthreads();
            regv += sh_gm[0];
            __syncthreads();
        }
        if (tid == 0) {
            g_regv = regv;
            if (out_size > 0) out[0] = 0.f;
        }
    }

    int cpk = 1;   // tid0-private: last observed packed (progress<<9)|nused

    // masked argmax + sum-exp over logits; uses per-thread regs L, am
    float L; bool am;
    auto do_reduce = [&](int nused) {
        float mlv = NINF;
        if (tid < NL) {
            bool irrel = (tid >= nused) && (tid < NPCC);
            mlv = (irrel || am) ? NINF : L;
        }
        {
            float rv = mlv; int ri = tid;
#pragma unroll
            for (int o = 16; o; o >>= 1) {
                float ov = __shfl_xor_sync(0xffffffffu, rv, o);
                int   oi = __shfl_xor_sync(0xffffffffu, ri, o);
                if (ov > rv || (ov == rv && oi < ri)) { rv = ov; ri = oi; }
            }
            if (lane == 0) { sh_red[warp] = rv; sh_redi[warp] = ri; }
        }
        __syncthreads();
        if (warp == 0) {
            float v2 = sh_red[lane]; int i2 = sh_redi[lane];
#pragma unroll
            for (int o = 16; o; o >>= 1) {
                float ov = __shfl_xor_sync(0xffffffffu, v2, o);
                int   oi = __shfl_xor_sync(0xffffffffu, i2, o);
                if (ov > v2 || (ov == v2 && oi < i2)) { v2 = ov; i2 = oi; }
            }
            if (lane == 0) { sh_gm[0] = v2; sh_mi[2] = i2; }
        }
        __syncthreads();
        float gmax = sh_gm[0];
        float pe = (mlv == NINF) ? 0.f : expf(mlv - gmax);
        pe = wsum(pe);
        if (lane == 0) sh_sum[warp] = pe;
        __syncthreads();
    };

    // ======================= pipelined speculative scan =======================
    for (int v = 1 + rank; v < NV; v += G) {
        if (tid < 16) sh_nbr[tid] = __ldg(&adj[v * DEG + tid]);
        __syncthreads();

        // ---- gate: wait for latest in-window committed neighbor ----
        if (tid == 0) {
            int maxu = -1;
#pragma unroll
            for (int t = 0; t < 16; t++) { int u = sh_nbr[t]; if (u < v && u > maxu) maxu = u; }
            if (maxu > (cpk >> 9)) {
                int pk;
                do { pk = ld_acq(&g_pp); } while ((pk >> 9) < maxu);
                cpk = pk;
            }
            sh_mi[1] = cpk & 511;   // nused guess for speculative mask
        }
        __syncthreads();

        // ---- Stage A: 16 rows, 2 half-rows per warp ----
        {
            int r = warp & 15, hf = warp >> 4;
            int u = sh_nbr[r];
            float d2 = 0.f; int c = -1;
            float4* hrow = (float4*)(sh_h + r * 512);
            const float4* a24 = (const float4*)sh_a2;
            if (u < v) {
                c = __ldcg(&g_colors[u]);
                const float4* zp = (const float4*)(g_z + (size_t)u * 512);
                const float4* wp = ((unsigned)c < NPCC)
                                 ? (const float4*)(W + (size_t)(512 + c) * 512) : (const float4*)0;
#pragma unroll
                for (int i = 0; i < 2; i++) {
                    int idx = hf * 64 + lane + 32 * i;
                    float4 hv = __ldcg(zp + idx);
                    if (wp) { float4 wv = __ldg(wp + idx);
                              hv.x += wv.x; hv.y += wv.y; hv.z += wv.z; hv.w += wv.w; }
                    hrow[idx] = hv;
                    d2 += dot4(hv, a24[idx]);
                }
                d2 = wsum(d2);
            } else {
                float4 zr = make_float4(0.f, 0.f, 0.f, 0.f);
#pragma unroll
                for (int i = 0; i < 2; i++) hrow[hf * 64 + lane + 32 * i] = zr;
            }
            if (lane == 0) { sh_e2[2 * r + hf] = d2; if (hf == 0) sh_nbrc[r] = c; }
        }
        __syncthreads();

        // ---- softmax (warps 0-15, replicated) + new_e = elu(attn @ h) ----
        if (warp < 16) {
            float ev;
            if (lane == 0) ev = 0.f;
            else if (lane < 17) {
                float t = sh_e2[2 * (lane - 1)] + sh_e2[2 * (lane - 1) + 1];
                ev = (t > 0.f) ? t : 0.2f * t;
            } else ev = NINF;
            float m = ev;
#pragma unroll
            for (int o = 16; o; o >>= 1) m = fmaxf(m, __shfl_xor_sync(0xffffffffu, m, o));
            float p = (lane < 17) ? expf(ev - m) : 0.f;
            float s = wsum(p);
            float attn = p / s;
            float acc = 0.f;
#pragma unroll
            for (int t = 1; t < 17; t++)
                acc += __shfl_sync(0xffffffffu, attn, t) * sh_h[(t - 1) * 512 + tid];
            sh_ne[tid] = (acc > 0.f) ? acc : expm1f(acc);
        }
        __syncthreads();

        // ---- P1 (fc1) + z partials ----
        {
            float4 r1 = gemv_part<64>((const float4*)g_T1 + (size_t)(kp * 64) * 128 + j4,
                                      sh_ne + kp * 64);
            float4 rz = gemv_part<64>((const float4*)W    + (size_t)(kp * 64) * 128 + j4,
                                      sh_ne + kp * 64);
            ((float4*)(sh_p1 + kp * 512))[j4] = r1;
            ((float4*)(sh_pz + kp * 512))[j4] = rz;
        }
        __syncthreads();
        if (tid < 512) {
            float s1 = 0.f, sz = 0.f;
#pragma unroll
            for (int q = 0; q < 8; q++) { s1 += sh_p1[q * 512 + tid]; sz += sh_pz[q * 512 + tid]; }
            float h = s1 + sh_b1[tid];
            sh_h1[tid] = (h > 0.f) ? h : 0.01f * h;
            __stcg(&g_z[(size_t)v * 512 + tid], sz);
        }
        __syncthreads();

        // ---- P2 (fc2) ----
        {
            float4 r2 = gemv_part<64>((const float4*)g_T2 + (size_t)(kp * 64) * 128 + j4,
                                      sh_h1 + kp * 64);
            ((float4*)(sh_p1 + kp * 512))[j4] = r2;
        }
        __syncthreads();
        if (tid < 512) {
            float s1 = 0.f;
#pragma unroll
            for (int q = 0; q < 8; q++) s1 += sh_p1[q * 512 + tid];
            float h = s1 + sh_b2[tid];
            sh_h2[tid] = (h > 0.f) ? h : 0.01f * h;
        }
        __syncthreads();

        // ---- P3 (fc3, k=400) ----
        {
            float4 r3 = gemv_part<50>((const float4*)g_T3 + (size_t)(kp * 50) * 128 + j4,
                                      sh_h2 + kp * 50);
            ((float4*)(sh_p1 + kp * 512))[j4] = r3;
        }
        __syncthreads();
        L = NINF; am = false;
        if (tid < NL) {
            float s1 = 0.f;
#pragma unroll
            for (int q = 0; q < 8; q++) s1 += sh_p1[q * 512 + tid];
            L = s1 + sh_b3[tid];
#pragma unroll
            for (int t = 0; t < 16; t++) am |= (sh_nbrc[t] == tid);
        }

        // ---- speculative masked reduce with guessed nused ----
        int guess = sh_mi[1];
        do_reduce(guess);

        // ---- commit: poll chain; on guess-hit finalize scalar-only ----
        if (tid == 0) {
            float gsum = 0.f;
            for (int w = 0; w < 32; w++) gsum += sh_sum[w];
            int pk;
            do { pk = ld_acq(&g_pp); } while ((pk >> 9) < v - 1);
            int actual = pk & 511;
            if (actual == guess) {
                int mi = sh_mi[2];
                int isnew = (mi == NPCC) ? 1 : 0;
                int chosen = isnew ? actual : mi;
                int nn = actual + isnew;
                __stcg(&g_colors[v], chosen);
                if (v < out_size) out[v] = (float)chosen;
                lpp += logf(1.f / gsum + 1e-8f) + 18.420680743952367f;
                st_rel(&g_pp, (v << 9) | nn);
                cpk = (v << 9) | nn;
                last_nn = nn;
                sh_mi[3] = 0;
            } else {
                sh_mi[3] = 1; sh_mi[1] = actual;
                cpk = pk;
            }
        }
        __syncthreads();
        if (sh_mi[3]) {   // rare: nused guess missed — redo with actual
            do_reduce(sh_mi[1]);
            if (tid == 0) {
                float gsum = 0.f;
                for (int w = 0; w < 32; w++) gsum += sh_sum[w];
                int actual = sh_mi[1];
                int mi = sh_mi[2];
                int isnew = (mi == NPCC) ? 1 : 0;
                int chosen = isnew ? actual : mi;
                int nn = actual + isnew;
                __stcg(&g_colors[v], chosen);
                if (v < out_size) out[v] = (float)chosen;
                lpp += logf(1.f / gsum + 1e-8f) + 18.420680743952367f;
                st_rel(&g_pp, (v << 9) | nn);
                cpk = (v << 9) | nn;
                last_nn = nn;
            }
            __syncthreads();
        }
    }

    // ---------------- finalize: deterministic lpp reduce + loss ----------------
    if (tid == 0) {
        g_lppp[rank] = lpp;
        st_rel(&g_done[rank], 1);
        if (rank == FINAL_RANK) {
            float tot = 0.f;
            for (int r = 0; r < G; r++) {
                while (ld_acq(&g_done[r]) == 0) {}
                tot += __ldcg(&g_lppp[r]);
            }
            if (out_size > NV) {
                float loss = ((float)last_nn - (float)baseline[0]) * tot / (float)NV
                           + 0.05f * __ldcg(&g_regv);
                out[NV] = loss;
            }
        }
    }
}

extern "C" void kernel_launch(void* const* d_in, const int* in_sizes, int n_in,
                              void* d_out, int out_size) {
    (void)in_sizes; (void)n_in;
    const int*   adj  = (const int*)d_in[0];
    const float* W    = (const float*)d_in[1];
    const float* a    = (const float*)d_in[2];
    const float* fc1w = (const float*)d_in[3];
    const float* fc1b = (const float*)d_in[4];
    const float* fc2w = (const float*)d_in[5];
    const float* fc2b = (const float*)d_in[6];
    const float* fc3w = (const float*)d_in[7];
    const float* fc3b = (const float*)d_in[8];
    const int*   bl   = (const int*)d_in[9];
    float* out = (float*)d_out;

    static int smem_set = 0;
    if (!smem_set) {
        cudaFuncSetAttribute(gc_main, cudaFuncAttributeMaxDynamicSharedMemorySize, SMEMB);
        smem_set = 1;
    }
    initk<<<128, 256>>>(fc1w, fc2w, fc3w);
    gc_main<<<G, TPB, SMEMB>>>(adj, W, a, fc1w, fc1b, fc2w, fc2b,
                               fc3w, fc3b, bl, out, out_size);
}

// round 11
// speedup vs baseline: 5.8789x; 1.0929x over previous
#include <cuda_runtime.h>
#include <math.h>
#include <stdint.h>

#define NV   8192
#define DEG  16
#define NPCC 256
#define NL   257
#define G    64
#define TPB  1024
#define NINF (-INFINITY)
#define FINAL_RANK ((NV - 2) % G)

// ---------------- persistent device scratch ----------------
__device__ __align__(16) float g_z[(size_t)NV * 512];
__device__ __align__(16) float g_T1[512 * 512];   // fc1^T interleaved [k][j4][c]
__device__ __align__(16) float g_T2[512 * 400];   // stride-100 packed fc2^T
__device__ __align__(16) float g_T3[400 * 260];   // stride-65 packed fc3^T (j pad 0)
__device__ int   g_colors[NV];
__device__ int   g_pp;              // packed (progress << 9) | nused  (release/acquire)
__device__ float g_regv;
__device__ float g_lppp[G];
__device__ int   g_done[G];

// ---------------- smem layout (float indices) ----------------
#define S_H    0        // 8192
#define S_P1   8192     // 4096
#define S_PZ   12288    // 4096
#define S_NE   16384    // 512
#define S_H1   16896    // 512
#define S_H2   17408    // 512
#define S_A2   17920    // 512
#define S_B1   18432    // 512
#define S_B2   18944    // 512
#define S_B3   19456    // 512 (257 used)
#define S_PMAX 19968    // 256
#define S_PSUM 20224    // 256
#define S_PIDX 20480    // 256 int
#define S_E2   20736    // 32
#define S_RED  20768    // 32
#define S_SWM  20800    // 8
#define S_SWS  20808    // 8
#define S_SWI  20816    // 8 int
#define S_NBR  20824    // 16 int
#define S_NBRC 20840    // 16 int
#define S_GM   20856    // 4 float (K, L256, E256)
#define S_TOT  20864
#define SMEMB  (S_TOT * 4)

__device__ __forceinline__ float wsum(float v) {
#pragma unroll
    for (int o = 16; o; o >>= 1) v += __shfl_xor_sync(0xffffffffu, v, o);
    return v;
}
__device__ __forceinline__ float wmax(float v) {
#pragma unroll
    for (int o = 16; o; o >>= 1) v = fmaxf(v, __shfl_xor_sync(0xffffffffu, v, o));
    return v;
}
__device__ __forceinline__ float dot4(float4 a, float4 b) {
    return a.x * b.x + a.y * b.y + a.z * b.z + a.w * b.w;
}
__device__ __forceinline__ int ld_acq(const int* p) {
    int v;
    asm volatile("ld.acquire.gpu.b32 %0, [%1];" : "=r"(v) : "l"(p) : "memory");
    return v;
}
__device__ __forceinline__ void st_rel(int* p, int v) {
    asm volatile("st.release.gpu.b32 [%0], %1;" :: "l"(p), "r"(v) : "memory");
}
// distance-aware backoff poll on g_pp until progress >= target
__device__ __forceinline__ int poll_pp(int target) {
    int pk = ld_acq(&g_pp);
    int d = target - (pk >> 9);
    while (d > 0) {
        if (d > 2) {
            int ns = d * 300; if (ns > 8000) ns = 8000;
            __nanosleep((unsigned)ns);
        }
        pk = ld_acq(&g_pp);
        d = target - (pk >> 9);
    }
    return pk;
}

// ---------------- init kernel (runs every launch) ----------------
__global__ void initk(const float* __restrict__ fc1w, const float* __restrict__ fc2w,
                      const float* __restrict__ fc3w) {
    int gt = blockIdx.x * blockDim.x + threadIdx.x;
    int GS = gridDim.x * blockDim.x;
    for (int d = gt; d < 512 * 512; d += GS) {
        int k = d >> 9, j = d & 511;
        g_T1[d] = fc1w[j * 512 + k];
    }
    for (int d = gt; d < 512 * 400; d += GS) {
        int c = d & 3, rest = d >> 2, j4 = rest % 100, k = rest / 100;
        g_T2[d] = fc2w[(j4 * 4 + c) * 512 + k];
    }
    for (int d = gt; d < 400 * 260; d += GS) {
        int c = d & 3, rest = d >> 2, j4 = rest % 65, k = rest / 65;
        int j = j4 * 4 + c;
        g_T3[d] = (j < NL) ? fc3w[j * 400 + k] : 0.f;
    }
    for (int i = gt; i < NV; i += GS) g_colors[i] = (i == 0) ? 0 : -1;
    for (int i = gt; i < 512; i += GS) g_z[i] = 0.f;
    if (gt < G) { g_done[gt] = 0; g_lppp[gt] = 0.f; }
    if (gt == 0) { g_pp = 1; g_regv = 0.f; }    // progress=0, nused=1
}

// column-GEMV partial: KQ k-steps (even), weights pre-offset, float4-stride STRIDE
template<int KQ, int STRIDE>
__device__ __forceinline__ float4 gemv_part(const float4* __restrict__ w,
                                            const float* __restrict__ x) {
    float4 e = make_float4(0.f, 0.f, 0.f, 0.f);
    float4 o = make_float4(0.f, 0.f, 0.f, 0.f);
#pragma unroll 8
    for (int k = 0; k < KQ; k += 2) {
        float x0 = x[k], x1 = x[k + 1];
        float4 w0 = __ldcg(w + (size_t)k * STRIDE);
        float4 w1 = __ldcg(w + (size_t)(k + 1) * STRIDE);
        e.x = fmaf(w0.x, x0, e.x); e.y = fmaf(w0.y, x0, e.y);
        e.z = fmaf(w0.z, x0, e.z); e.w = fmaf(w0.w, x0, e.w);
        o.x = fmaf(w1.x, x1, o.x); o.y = fmaf(w1.y, x1, o.y);
        o.z = fmaf(w1.z, x1, o.z); o.w = fmaf(w1.w, x1, o.w);
    }
    return make_float4(e.x + o.x, e.y + o.y, e.z + o.z, e.w + o.w);
}

__global__ void __launch_bounds__(TPB, 1)
gc_main(const int* __restrict__ adj, const float* __restrict__ W,
        const float* __restrict__ a, const float* __restrict__ fc1w,
        const float* __restrict__ fc1b, const float* __restrict__ fc2w,
        const float* __restrict__ fc2b, const float* __restrict__ fc3w,
        const float* __restrict__ fc3b, const int* __restrict__ baseline,
        float* __restrict__ out, int out_size)
{
    extern __shared__ __align__(16) float sm[];
    int*   smi     = (int*)sm;
    float* sh_h    = sm + S_H;
    float* sh_p1   = sm + S_P1;
    float* sh_pz   = sm + S_PZ;
    float* sh_ne   = sm + S_NE;
    float* sh_h1   = sm + S_H1;
    float* sh_h2   = sm + S_H2;
    float* sh_a2   = sm + S_A2;
    float* sh_b1   = sm + S_B1;
    float* sh_b2   = sm + S_B2;
    float* sh_b3   = sm + S_B3;
    float* sh_pmax = sm + S_PMAX;
    float* sh_psum = sm + S_PSUM;
    int*   sh_pidx = smi + S_PIDX;
    float* sh_e2   = sm + S_E2;
    float* sh_red  = sm + S_RED;
    float* sh_swm  = sm + S_SWM;
    float* sh_sws  = sm + S_SWS;
    int*   sh_swi  = smi + S_SWI;
    int*   sh_nbr  = smi + S_NBR;
    int*   sh_nbrc = smi + S_NBRC;
    float* sh_gm   = sm + S_GM;

    const int rank = blockIdx.x;
    const int tid  = threadIdx.x;
    const int warp = tid >> 5, lane = tid & 31;
    const int j4 = tid & 127, kp = tid >> 7;        // P1/z: 128 x 8
    const int j4b = tid % 100, kpb = tid / 100;     // P2: 100 x 8 (800 threads)
    const int j4c = tid % 65,  kpc = tid / 65;      // P3: 65 x 8 (520 threads)

    float lpp = 0.f;
    int last_nn = 0;

    if (tid < 512) {
        sh_a2[tid] = a[512 + tid];
        sh_b1[tid] = fc1b[tid];
        sh_b2[tid] = (tid < 400) ? fc2b[tid] : 0.f;
        sh_b3[tid] = (tid < NL)  ? fc3b[tid] : 0.f;
    }
    __syncthreads();

    // rank 0: Frobenius norms before its first commit
    if (rank == 0) {
        float s[4] = {0.f, 0.f, 0.f, 0.f};
        for (int i = tid; i < 768 * 512; i += TPB) { float x = W[i];    s[0] += x * x; }
        for (int i = tid; i < 512 * 512; i += TPB) { float x = fc1w[i]; s[1] += x * x; }
        for (int i = tid; i < 400 * 512; i += TPB) { float x = fc2w[i]; s[2] += x * x; }
        for (int i = tid; i < 257 * 400; i += TPB) { float x = fc3w[i]; s[3] += x * x; }
        float regv = 0.f;
#pragma unroll
        for (int m = 0; m < 4; m++) {
            float w = wsum(s[m]);
            __syncthreads();
            if (lane == 0) sh_red[warp] = w;
            __syncthreads();
            if (warp == 0) {
                float v2 = sh_red[lane];
                v2 = wsum(v2);
                if (lane == 0) sh_gm[0] = sqrtf(v2);
            }
            __syncthreads();
            regv += sh_gm[0];
            __syncthreads();
        }
        if (tid == 0) {
            g_regv = regv;
            if (out_size > 0) out[0] = 0.f;
        }
    }

    int cprog = 0;   // tid0-private: highest observed committed vertex

    // ======================= pipelined speculative scan =======================
    for (int v = 1 + rank; v < NV; v += G) {
        if (tid < 16) sh_nbr[tid] = __ldg(&adj[v * DEG + tid]);
        __syncthreads();

        // ---- gate: wait until the latest in-window neighbor is committed ----
        if (tid == 0) {
            int maxu = -1;
#pragma unroll
            for (int t = 0; t < 16; t++) { int u = sh_nbr[t]; if (u < v && u > maxu) maxu = u; }
            if (maxu > cprog) cprog = poll_pp(maxu) >> 9;
        }
        __syncthreads();

        // ---- Stage A: 16 rows, 2 half-rows per warp ----
        {
            int r = warp & 15, hf = warp >> 4;
            int u = sh_nbr[r];
            float d2 = 0.f; int c = -1;
            float4* hrow = (float4*)(sh_h + r * 512);
            const float4* a24 = (const float4*)sh_a2;
            if (u < v) {
                c = __ldcg(&g_colors[u]);
                const float4* zp = (const float4*)(g_z + (size_t)u * 512);
                const float4* wp = ((unsigned)c < NPCC)
                                 ? (const float4*)(W + (size_t)(512 + c) * 512) : (const float4*)0;
#pragma unroll
                for (int i = 0; i < 2; i++) {
                    int idx = hf * 64 + lane + 32 * i;
                    float4 hv = __ldcg(zp + idx);
                    if (wp) { float4 wv = __ldg(wp + idx);
                              hv.x += wv.x; hv.y += wv.y; hv.z += wv.z; hv.w += wv.w; }
                    hrow[idx] = hv;
                    d2 += dot4(hv, a24[idx]);
                }
                d2 = wsum(d2);
            } else {
                float4 zr = make_float4(0.f, 0.f, 0.f, 0.f);
#pragma unroll
                for (int i = 0; i < 2; i++) hrow[hf * 64 + lane + 32 * i] = zr;
            }
            if (lane == 0) { sh_e2[2 * r + hf] = d2; if (hf == 0) sh_nbrc[r] = c; }
        }
        __syncthreads();

        // ---- softmax (warps 0-15, replicated) + new_e = elu(attn @ h) ----
        if (warp < 16) {
            float ev;
            if (lane == 0) ev = 0.f;
            else if (lane < 17) {
                float t = sh_e2[2 * (lane - 1)] + sh_e2[2 * (lane - 1) + 1];
                ev = (t > 0.f) ? t : 0.2f * t;
            } else ev = NINF;
            float m = ev;
#pragma unroll
            for (int o = 16; o; o >>= 1) m = fmaxf(m, __shfl_xor_sync(0xffffffffu, m, o));
            float p = (lane < 17) ? expf(ev - m) : 0.f;
            float s = wsum(p);
            float attn = p / s;
            float acc = 0.f;
#pragma unroll
            for (int t = 1; t < 17; t++)
                acc += __shfl_sync(0xffffffffu, attn, t) * sh_h[(t - 1) * 512 + tid];
            sh_ne[tid] = (acc > 0.f) ? acc : expm1f(acc);
        }
        __syncthreads();

        // ---- P1 (fc1) + z partials ----
        {
            float4 r1 = gemv_part<64, 128>((const float4*)g_T1 + (size_t)(kp * 64) * 128 + j4,
                                           sh_ne + kp * 64);
            float4 rz = gemv_part<64, 128>((const float4*)W    + (size_t)(kp * 64) * 128 + j4,
                                           sh_ne + kp * 64);
            ((float4*)(sh_p1 + kp * 512))[j4] = r1;
            ((float4*)(sh_pz + kp * 512))[j4] = rz;
        }
        __syncthreads();
        if (tid < 512) {
            float s1 = 0.f, sz = 0.f;
#pragma unroll
            for (int q = 0; q < 8; q++) { s1 += sh_p1[q * 512 + tid]; sz += sh_pz[q * 512 + tid]; }
            float h = s1 + sh_b1[tid];
            sh_h1[tid] = (h > 0.f) ? h : 0.01f * h;
            __stcg(&g_z[(size_t)v * 512 + tid], sz);
        }
        __syncthreads();

        // ---- P2 (fc2, packed stride 100) ----
        if (tid < 800) {
            float4 r2 = gemv_part<64, 100>((const float4*)g_T2 + (size_t)(kpb * 64) * 100 + j4b,
                                           sh_h1 + kpb * 64);
            ((float4*)(sh_p1 + kpb * 512))[j4b] = r2;
        }
        __syncthreads();
        if (tid < 400) {
            float s1 = 0.f;
#pragma unroll
            for (int q = 0; q < 8; q++) s1 += sh_p1[q * 512 + tid];
            float h = s1 + sh_b2[tid];
            sh_h2[tid] = (h > 0.f) ? h : 0.01f * h;
        }
        __syncthreads();

        // ---- P3 (fc3, packed stride 65, k=400) ----
        if (tid < 520) {
            float4 r3 = gemv_part<50, 65>((const float4*)g_T3 + (size_t)(kpc * 50) * 65 + j4c,
                                          sh_h2 + kpc * 50);
            ((float4*)(sh_p1 + kpc * 512))[j4c] = r3;
        }
        __syncthreads();
        float L = NINF; bool am = false;
        if (tid < NL) {
            float s1 = 0.f;
#pragma unroll
            for (int q = 0; q < 8; q++) s1 += sh_p1[q * 512 + tid];
            L = s1 + sh_b3[tid];
#pragma unroll
            for (int t = 0; t < 16; t++) am |= (sh_nbrc[t] == tid);
        }

        // ---- K = unmasked max over all 257 logits ----
        {
            float km = wmax(L);
            if (lane == 0) sh_red[warp] = km;
        }
        __syncthreads();
        if (warp == 0) {
            float v2 = sh_red[lane];
            v2 = wmax(v2);
            if (lane == 0) sh_gm[0] = v2;
        }
        if (tid == 256) { sh_gm[1] = L; }
        __syncthreads();
        const float K = sh_gm[0];

        // ---- prefix scan over j<256 (adjacency pre-masked): max/argmax/sum-exp ----
        // registers v_, i_, e_ carried across the barrier (single scan pass)
        float v_ = NINF, e_ = 0.f; int i_ = tid;
        if (tid < 256) {
            v_ = am ? NINF : L;
            e_ = am ? 0.f : expf(L - K);
#pragma unroll
            for (int o = 1; o < 32; o <<= 1) {
                float pv = __shfl_up_sync(0xffffffffu, v_, o);
                int   pi = __shfl_up_sync(0xffffffffu, i_, o);
                float pe = __shfl_up_sync(0xffffffffu, e_, o);
                if (lane >= o) { if (pv >= v_) { v_ = pv; i_ = pi; } e_ += pe; }
            }
            if (lane == 31) { sh_swm[warp] = v_; sh_swi[warp] = i_; sh_sws[warp] = e_; }
        }
        if (tid == 256) sh_gm[2] = expf(L - K);
        __syncthreads();
        if (tid < 256) {
            float bm = NINF; int bi = 0; float bs = 0.f;
#pragma unroll
            for (int w2 = 0; w2 < 8; w2++) {
                if (w2 < warp) {
                    float tm = sh_swm[w2];
                    if (tm > bm) { bm = tm; bi = sh_swi[w2]; }
                    bs += sh_sws[w2];
                }
            }
            if (bm >= v_) { v_ = bm; i_ = bi; }   // earlier warp wins ties
            e_ += bs;
            sh_pmax[tid] = v_; sh_pidx[tid] = i_; sh_psum[tid] = e_;
        }
        __syncthreads();

        // ---- commit: poll chain, scalar lookup only ----
        if (tid == 0) {
            int pk = poll_pp(v - 1);
            int n  = pk & 511;                   // nused in [1, 256]
            float m  = sh_pmax[n - 1];
            int   mi = sh_pidx[n - 1];
            float s  = sh_psum[n - 1];
            float l2 = sh_gm[1], e2 = sh_gm[2];
            int   isnew  = (l2 > m) ? 1 : 0;     // lower index wins ties
            float gmax   = isnew ? l2 : m;
            int   chosen = isnew ? n : mi;
            int   nn     = n + isnew;
            float maxp   = expf(gmax - K) / (s + e2);
            __stcg(&g_colors[v], chosen);
            if (v < out_size) out[v] = (float)chosen;
            lpp += logf(maxp + 1e-8f) + 18.420680743952367f;
            st_rel(&g_pp, (v << 9) | nn);
            cprog = v;
            last_nn = nn;
        }
        __syncthreads();
    }

    // ---------------- finalize: deterministic lpp reduce + loss ----------------
    if (tid == 0) {
        g_lppp[rank] = lpp;
        st_rel(&g_done[rank], 1);
        if (rank == FINAL_RANK) {
            float tot = 0.f;
            for (int r = 0; r < G; r++) {
                while (ld_acq(&g_done[r]) == 0) __nanosleep(200);
                tot += __ldcg(&g_lppp[r]);
            }
            if (out_size > NV) {
                float loss = ((float)last_nn - (float)baseline[0]) * tot / (float)NV
                           + 0.05f * __ldcg(&g_regv);
                out[NV] = loss;
            }
        }
    }
}

extern "C" void kernel_launch(void* const* d_in, const int* in_sizes, int n_in,
                              void* d_out, int out_size) {
    (void)in_sizes; (void)n_in;
    const int*   adj  = (const int*)d_in[0];
    const float* W    = (const float*)d_in[1];
    const float* a    = (const float*)d_in[2];
    const float* fc1w = (const float*)d_in[3];
    const float* fc1b = (const float*)d_in[4];
    const float* fc2w = (const float*)d_in[5];
    const float* fc2b = (const float*)d_in[6];
    const float* fc3w = (const float*)d_in[7];
    const float* fc3b = (const float*)d_in[8];
    const int*   bl   = (const int*)d_in[9];
    float* out = (float*)d_out;

    static int smem_set = 0;
    if (!smem_set) {
        cudaFuncSetAttribute(gc_main, cudaFuncAttributeMaxDynamicSharedMemorySize, SMEMB);
        smem_set = 1;
    }
    initk<<<128, 256>>>(fc1w, fc2w, fc3w);
    gc_main<<<G, TPB, SMEMB>>>(adj, W, a, fc1w, fc1b, fc2w, fc2b,
                               fc3w, fc3b, bl, out, out_size);
}

// round 12
// speedup vs baseline: 7.8748x; 1.3395x over previous
#include <cuda_runtime.h>
#include <math.h>
#include <stdint.h>

#define NV   8192
#define DEG  16
#define NPCC 256
#define NL   257
#define G    64
#define TPB  1024
#define NINF (-INFINITY)
#define FINAL_RANK ((NV - 2) % G)

// ---------------- persistent device scratch ----------------
__device__ __align__(16) float g_z[(size_t)NV * 512];
__device__ __align__(16) float g_T1[512 * 512];   // fc1^T interleaved [k][j4][c]
__device__ __align__(16) float g_T2[512 * 400];   // stride-100 packed fc2^T
__device__ __align__(16) float g_T3[400 * 260];   // stride-65 packed fc3^T (j pad 0)
__device__ int   g_colors[NV];
__device__ int   g_pp;              // packed (progress << 9) | nused  (release, for gates)
__device__ int   g_mbox[G];         // per-rank chain mailbox: (v<<18)|(chosen<<9)|nused
__device__ float g_regv;
__device__ float g_lppp[G];
__device__ int   g_done[G];

// ---------------- smem layout (float indices) ----------------
#define S_H    0        // 8192
#define S_P1   8192     // 4096
#define S_PZ   12288    // 4096
#define S_NE   16384    // 512
#define S_H1   16896    // 512
#define S_H2   17408    // 512
#define S_A2   17920    // 512
#define S_B1   18432    // 512
#define S_B2   18944    // 512
#define S_B3   19456    // 512 (257 used)
#define S_CTF  19968    // 256 float: lp(n) table
#define S_CTI  20224    // 256 int: (chosen<<9)|nn table
#define S_E2   20736    // 32
#define S_RED  20768    // 32
#define S_SWM  20800    // 8
#define S_SWS  20808    // 8
#define S_SWI  20816    // 8 int
#define S_NBR  20824    // 16 int
#define S_NBRC 20840    // 16 int
#define S_GM   20856    // 4 float (K, L256, E256)
#define S_TOT  20864
#define SMEMB  (S_TOT * 4)

__device__ __forceinline__ float wsum(float v) {
#pragma unroll
    for (int o = 16; o; o >>= 1) v += __shfl_xor_sync(0xffffffffu, v, o);
    return v;
}
__device__ __forceinline__ float wmax(float v) {
#pragma unroll
    for (int o = 16; o; o >>= 1) v = fmaxf(v, __shfl_xor_sync(0xffffffffu, v, o));
    return v;
}
__device__ __forceinline__ float dot4(float4 a, float4 b) {
    return a.x * b.x + a.y * b.y + a.z * b.z + a.w * b.w;
}
__device__ __forceinline__ int ld_acq(const int* p) {
    int v;
    asm volatile("ld.acquire.gpu.b32 %0, [%1];" : "=r"(v) : "l"(p) : "memory");
    return v;
}
__device__ __forceinline__ void st_rel(int* p, int v) {
    asm volatile("st.release.gpu.b32 [%0], %1;" :: "l"(p), "r"(v) : "memory");
}
__device__ __forceinline__ int ld_rlx(const int* p) {
    int v;
    asm volatile("ld.relaxed.gpu.b32 %0, [%1];" : "=r"(v) : "l"(p) : "memory");
    return v;
}
__device__ __forceinline__ void st_rlx(int* p, int v) {
    asm volatile("st.relaxed.gpu.b32 [%0], %1;" :: "l"(p), "r"(v) : "memory");
}
// backoff poll on g_pp until progress >= target (gate path only)
__device__ __forceinline__ int poll_pp(int target) {
    int pk = ld_acq(&g_pp);
    int d = target - (pk >> 9);
    while (d > 0) {
        if (d > 2) {
            int ns = d * 100; if (ns > 3000) ns = 3000;
            __nanosleep((unsigned)ns);
        }
        pk = ld_acq(&g_pp);
        d = target - (pk >> 9);
    }
    return pk;
}

// ---------------- init kernel (runs every launch) ----------------
__global__ void initk(const float* __restrict__ fc1w, const float* __restrict__ fc2w,
                      const float* __restrict__ fc3w) {
    int gt = blockIdx.x * blockDim.x + threadIdx.x;
    int GS = gridDim.x * blockDim.x;
    for (int d = gt; d < 512 * 512; d += GS) {
        int k = d >> 9, j = d & 511;
        g_T1[d] = fc1w[j * 512 + k];
    }
    for (int d = gt; d < 512 * 400; d += GS) {
        int c = d & 3, rest = d >> 2, j4 = rest % 100, k = rest / 100;
        g_T2[d] = fc2w[(j4 * 4 + c) * 512 + k];
    }
    for (int d = gt; d < 400 * 260; d += GS) {
        int c = d & 3, rest = d >> 2, j4 = rest % 65, k = rest / 65;
        int j = j4 * 4 + c;
        g_T3[d] = (j < NL) ? fc3w[j * 400 + k] : 0.f;
    }
    for (int i = gt; i < NV; i += GS) g_colors[i] = (i == 0) ? 0 : -1;
    for (int i = gt; i < 512; i += GS) g_z[i] = 0.f;
    if (gt < G) {
        g_done[gt] = 0; g_lppp[gt] = 0.f;
        // mbox[0] = vertex-0 commit word: v=0, chosen=0, nused=1; others invalid
        g_mbox[gt] = (gt == 0) ? 1 : 0x7fffffff;
    }
    if (gt == 0) { g_pp = 1; g_regv = 0.f; }    // progress=0, nused=1
}

// column-GEMV partial: KQ k-steps (even), weights pre-offset, float4-stride STRIDE
template<int KQ, int STRIDE>
__device__ __forceinline__ float4 gemv_part(const float4* __restrict__ w,
                                            const float* __restrict__ x) {
    float4 e = make_float4(0.f, 0.f, 0.f, 0.f);
    float4 o = make_float4(0.f, 0.f, 0.f, 0.f);
#pragma unroll 8
    for (int k = 0; k < KQ; k += 2) {
        float x0 = x[k], x1 = x[k + 1];
        float4 w0 = __ldcg(w + (size_t)k * STRIDE);
        float4 w1 = __ldcg(w + (size_t)(k + 1) * STRIDE);
        e.x = fmaf(w0.x, x0, e.x); e.y = fmaf(w0.y, x0, e.y);
        e.z = fmaf(w0.z, x0, e.z); e.w = fmaf(w0.w, x0, e.w);
        o.x = fmaf(w1.x, x1, o.x); o.y = fmaf(w1.y, x1, o.y);
        o.z = fmaf(w1.z, x1, o.z); o.w = fmaf(w1.w, x1, o.w);
    }
    return make_float4(e.x + o.x, e.y + o.y, e.z + o.z, e.w + o.w);
}

__global__ void __launch_bounds__(TPB, 1)
gc_main(const int* __restrict__ adj, const float* __restrict__ W,
        const float* __restrict__ a, const float* __restrict__ fc1w,
        const float* __restrict__ fc1b, const float* __restrict__ fc2w,
        const float* __restrict__ fc2b, const float* __restrict__ fc3w,
        const float* __restrict__ fc3b, const int* __restrict__ baseline,
        float* __restrict__ out, int out_size)
{
    extern __shared__ __align__(16) float sm[];
    int*   smi     = (int*)sm;
    float* sh_h    = sm + S_H;
    float* sh_p1   = sm + S_P1;
    float* sh_pz   = sm + S_PZ;
    float* sh_ne   = sm + S_NE;
    float* sh_h1   = sm + S_H1;
    float* sh_h2   = sm + S_H2;
    float* sh_a2   = sm + S_A2;
    float* sh_b1   = sm + S_B1;
    float* sh_b2   = sm + S_B2;
    float* sh_b3   = sm + S_B3;
    float* sh_ctf  = sm + S_CTF;
    int*   sh_cti  = smi + S_CTI;
    float* sh_e2   = sm + S_E2;
    float* sh_red  = sm + S_RED;
    float* sh_swm  = sm + S_SWM;
    float* sh_sws  = sm + S_SWS;
    int*   sh_swi  = smi + S_SWI;
    int*   sh_nbr  = smi + S_NBR;
    int*   sh_nbrc = smi + S_NBRC;
    float* sh_gm   = sm + S_GM;

    const int rank = blockIdx.x;
    const int tid  = threadIdx.x;
    const int warp = tid >> 5, lane = tid & 31;
    const int j4 = tid & 127, kp = tid >> 7;        // P1/z: 128 x 8
    const int j4b = tid % 100, kpb = tid / 100;     // P2: 100 x 8 (800 threads)
    const int j4c = tid % 65,  kpc = tid / 65;      // P3: 65 x 8 (520 threads)

    float lpp = 0.f;
    int last_nn = 0;

    if (tid < 512) {
        sh_a2[tid] = a[512 + tid];
        sh_b1[tid] = fc1b[tid];
        sh_b2[tid] = (tid < 400) ? fc2b[tid] : 0.f;
        sh_b3[tid] = (tid < NL)  ? fc3b[tid] : 0.f;
    }
    __syncthreads();

    // rank 0: Frobenius norms before its first commit
    if (rank == 0) {
        float s[4] = {0.f, 0.f, 0.f, 0.f};
        for (int i = tid; i < 768 * 512; i += TPB) { float x = W[i];    s[0] += x * x; }
        for (int i = tid; i < 512 * 512; i += TPB) { float x = fc1w[i]; s[1] += x * x; }
        for (int i = tid; i < 400 * 512; i += TPB) { float x = fc2w[i]; s[2] += x * x; }
        for (int i = tid; i < 257 * 400; i += TPB) { float x = fc3w[i]; s[3] += x * x; }
        float regv = 0.f;
#pragma unroll
        for (int m = 0; m < 4; m++) {
            float w = wsum(s[m]);
            __syncthreads();
            if (lane == 0) sh_red[warp] = w;
            __syncthreads();
            if (warp == 0) {
                float v2 = sh_red[lane];
                v2 = wsum(v2);
                if (lane == 0) sh_gm[0] = sqrtf(v2);
            }
            __syncthreads();
            regv += sh_gm[0];
            __syncthreads();
        }
        if (tid == 0) {
            g_regv = regv;
            if (out_size > 0) out[0] = 0.f;
        }
    }

    int cprog = 0;   // tid0-private: highest observed committed vertex

    // ======================= pipelined speculative scan =======================
    for (int v = 1 + rank; v < NV; v += G) {
        if (tid < 16) sh_nbr[tid] = __ldg(&adj[v * DEG + tid]);
        __syncthreads();

        // ---- gate: wait until the latest in-window neighbor is committed ----
        if (tid == 0) {
            int maxu = -1;
#pragma unroll
            for (int t = 0; t < 16; t++) { int u = sh_nbr[t]; if (u < v && u > maxu) maxu = u; }
            if (maxu > cprog) cprog = poll_pp(maxu) >> 9;
        }
        __syncthreads();

        // ---- Stage A: 16 rows, 2 half-rows per warp ----
        {
            int r = warp & 15, hf = warp >> 4;
            int u = sh_nbr[r];
            float d2 = 0.f; int c = -1;
            float4* hrow = (float4*)(sh_h + r * 512);
            const float4* a24 = (const float4*)sh_a2;
            if (u < v) {
                c = __ldcg(&g_colors[u]);
                const float4* zp = (const float4*)(g_z + (size_t)u * 512);
                const float4* wp = ((unsigned)c < NPCC)
                                 ? (const float4*)(W + (size_t)(512 + c) * 512) : (const float4*)0;
#pragma unroll
                for (int i = 0; i < 2; i++) {
                    int idx = hf * 64 + lane + 32 * i;
                    float4 hv = __ldcg(zp + idx);
                    if (wp) { float4 wv = __ldg(wp + idx);
                              hv.x += wv.x; hv.y += wv.y; hv.z += wv.z; hv.w += wv.w; }
                    hrow[idx] = hv;
                    d2 += dot4(hv, a24[idx]);
                }
                d2 = wsum(d2);
            } else {
                float4 zr = make_float4(0.f, 0.f, 0.f, 0.f);
#pragma unroll
                for (int i = 0; i < 2; i++) hrow[hf * 64 + lane + 32 * i] = zr;
            }
            if (lane == 0) { sh_e2[2 * r + hf] = d2; if (hf == 0) sh_nbrc[r] = c; }
        }
        __syncthreads();

        // ---- softmax (warps 0-15, replicated) + new_e = elu(attn @ h) ----
        if (warp < 16) {
            float ev;
            if (lane == 0) ev = 0.f;
            else if (lane < 17) {
                float t = sh_e2[2 * (lane - 1)] + sh_e2[2 * (lane - 1) + 1];
                ev = (t > 0.f) ? t : 0.2f * t;
            } else ev = NINF;
            float m = ev;
#pragma unroll
            for (int o = 16; o; o >>= 1) m = fmaxf(m, __shfl_xor_sync(0xffffffffu, m, o));
            float p = (lane < 17) ? expf(ev - m) : 0.f;
            float s = wsum(p);
            float attn = p / s;
            float acc = 0.f;
#pragma unroll
            for (int t = 1; t < 17; t++)
                acc += __shfl_sync(0xffffffffu, attn, t) * sh_h[(t - 1) * 512 + tid];
            sh_ne[tid] = (acc > 0.f) ? acc : expm1f(acc);
        }
        __syncthreads();

        // ---- P1 (fc1) + z partials ----
        {
            float4 r1 = gemv_part<64, 128>((const float4*)g_T1 + (size_t)(kp * 64) * 128 + j4,
                                           sh_ne + kp * 64);
            float4 rz = gemv_part<64, 128>((const float4*)W    + (size_t)(kp * 64) * 128 + j4,
                                           sh_ne + kp * 64);
            ((float4*)(sh_p1 + kp * 512))[j4] = r1;
            ((float4*)(sh_pz + kp * 512))[j4] = rz;
        }
        __syncthreads();
        if (tid < 512) {
            float s1 = 0.f, sz = 0.f;
#pragma unroll
            for (int q = 0; q < 8; q++) { s1 += sh_p1[q * 512 + tid]; sz += sh_pz[q * 512 + tid]; }
            float h = s1 + sh_b1[tid];
            sh_h1[tid] = (h > 0.f) ? h : 0.01f * h;
            __stcg(&g_z[(size_t)v * 512 + tid], sz);
        }
        __syncthreads();

        // ---- P2 (fc2, packed stride 100) ----
        if (tid < 800) {
            float4 r2 = gemv_part<64, 100>((const float4*)g_T2 + (size_t)(kpb * 64) * 100 + j4b,
                                           sh_h1 + kpb * 64);
            ((float4*)(sh_p1 + kpb * 512))[j4b] = r2;
        }
        __syncthreads();
        if (tid < 400) {
            float s1 = 0.f;
#pragma unroll
            for (int q = 0; q < 8; q++) s1 += sh_p1[q * 512 + tid];
            float h = s1 + sh_b2[tid];
            sh_h2[tid] = (h > 0.f) ? h : 0.01f * h;
        }
        __syncthreads();

        // ---- P3 (fc3, packed stride 65, k=400) ----
        if (tid < 520) {
            float4 r3 = gemv_part<50, 65>((const float4*)g_T3 + (size_t)(kpc * 50) * 65 + j4c,
                                          sh_h2 + kpc * 50);
            ((float4*)(sh_p1 + kpc * 512))[j4c] = r3;
        }
        __syncthreads();
        float L = NINF; bool am = false;
        if (tid < NL) {
            float s1 = 0.f;
#pragma unroll
            for (int q = 0; q < 8; q++) s1 += sh_p1[q * 512 + tid];
            L = s1 + sh_b3[tid];
#pragma unroll
            for (int t = 0; t < 16; t++) am |= (sh_nbrc[t] == tid);
        }

        // ---- K = unmasked max over all 257 logits ----
        {
            float km = wmax(L);
            if (lane == 0) sh_red[warp] = km;
        }
        __syncthreads();
        if (warp == 0) {
            float v2 = sh_red[lane];
            v2 = wmax(v2);
            if (lane == 0) sh_gm[0] = v2;
        }
        if (tid == 256) { sh_gm[1] = L; }
        __syncthreads();
        const float K = sh_gm[0];

        // ---- prefix scan over j<256 (adjacency pre-masked): max/argmax/sum-exp ----
        float v_ = NINF, e_ = 0.f; int i_ = tid;
        if (tid < 256) {
            v_ = am ? NINF : L;
            e_ = am ? 0.f : expf(L - K);
#pragma unroll
            for (int o = 1; o < 32; o <<= 1) {
                float pv = __shfl_up_sync(0xffffffffu, v_, o);
                int   pi = __shfl_up_sync(0xffffffffu, i_, o);
                float pe = __shfl_up_sync(0xffffffffu, e_, o);
                if (lane >= o) { if (pv >= v_) { v_ = pv; i_ = pi; } e_ += pe; }
            }
            if (lane == 31) { sh_swm[warp] = v_; sh_swi[warp] = i_; sh_sws[warp] = e_; }
        }
        if (tid == 256) sh_gm[2] = expf(L - K);
        __syncthreads();
        // ---- finish prefix + precompute FULL commit table for every nused=tid+1 ----
        if (tid < 256) {
            float bm = NINF; int bi = 0; float bs = 0.f;
#pragma unroll
            for (int w2 = 0; w2 < 8; w2++) {
                if (w2 < warp) {
                    float tm = sh_swm[w2];
                    if (tm > bm) { bm = tm; bi = sh_swi[w2]; }
                    bs += sh_sws[w2];
                }
            }
            if (bm >= v_) { v_ = bm; i_ = bi; }   // earlier warp wins ties
            e_ += bs;
            // thread tid holds prefix over colors [0..tid] == tables for n = tid+1
            int   n      = tid + 1;
            float l2     = sh_gm[1];
            float e2     = sh_gm[2];
            int   isnew  = (l2 > v_) ? 1 : 0;     // lower index wins ties
            float gmax   = isnew ? l2 : v_;
            int   chosen = isnew ? n : i_;
            int   nn     = n + isnew;
            float maxp   = expf(gmax - K) / (e_ + e2);
            sh_ctf[tid] = logf(maxp + 1e-8f) + 18.420680743952367f;
            sh_cti[tid] = (chosen << 9) | nn;
        }
        __syncthreads();

        // ---- commit: spin own mailbox, table lookup, relay — minimal hop ----
        if (tid == 0) {
            int w;
            do { w = ld_rlx(&g_mbox[rank]); } while ((w >> 18) != v - 1);
            int n  = w & 511;                    // nused in [1, 256]
            int ci = sh_cti[n - 1];
            int chosen = ci >> 9, nn = ci & 511;
            st_rlx(&g_mbox[v & (G - 1)], (v << 18) | ci);   // chain hop done
            __stcg(&g_colors[v], chosen);
            if (v < out_size) out[v] = (float)chosen;
            lpp += sh_ctf[n - 1];
            st_rel(&g_pp, (v << 9) | nn);        // gates: orders colors/z/out
            cprog = v;
            last_nn = nn;
        }
        __syncthreads();
    }

    // ---------------- finalize: deterministic lpp reduce + loss ----------------
    if (tid == 0) {
        g_lppp[rank] = lpp;
        st_rel(&g_done[rank], 1);
        if (rank == FINAL_RANK) {
            float tot = 0.f;
            for (int r = 0; r < G; r++) {
                while (ld_acq(&g_done[r]) == 0) __nanosleep(200);
                tot += __ldcg(&g_lppp[r]);
            }
            if (out_size > NV) {
                float loss = ((float)last_nn - (float)baseline[0]) * tot / (float)NV
                           + 0.05f * __ldcg(&g_regv);
                out[NV] = loss;
            }
        }
    }
}

extern "C" void kernel_launch(void* const* d_in, const int* in_sizes, int n_in,
                              void* d_out, int out_size) {
    (void)in_sizes; (void)n_in;
    const int*   adj  = (const int*)d_in[0];
    const float* W    = (const float*)d_in[1];
    const float* a    = (const float*)d_in[2];
    const float* fc1w = (const float*)d_in[3];
    const float* fc1b = (const float*)d_in[4];
    const float* fc2w = (const float*)d_in[5];
    const float* fc2b = (const float*)d_in[6];
    const float* fc3w = (const float*)d_in[7];
    const float* fc3b = (const float*)d_in[8];
    const int*   bl   = (const int*)d_in[9];
    float* out = (float*)d_out;

    static int smem_set = 0;
    if (!smem_set) {
        cudaFuncSetAttribute(gc_main, cudaFuncAttributeMaxDynamicSharedMemorySize, SMEMB);
        smem_set = 1;
    }
    initk<<<128, 256>>>(fc1w, fc2w, fc3w);
    gc_main<<<G, TPB, SMEMB>>>(adj, W, a, fc1w, fc1b, fc2w, fc2b,
                               fc3w, fc3b, bl, out, out_size);
}

// round 14
// speedup vs baseline: 9.2658x; 1.1766x over previous
#include <cuda_runtime.h>
#include <math.h>
#include <stdint.h>

#define NV   8192
#define DEG  16
#define NPCC 256
#define NL   257
#define G    64        // pairs
#define TPB  1024
#define NINF (-INFINITY)
#define FINAL_PAIR ((NV - 2) % G)   // 62

// ---------------- persistent device scratch ----------------
__device__ __align__(16) float g_z[(size_t)NV * 512];
__device__ __align__(16) float g_T1[512 * 512];   // fc1^T interleaved [k][j4][c]
__device__ __align__(16) float g_T2[512 * 400];   // stride-100 packed fc2^T
__device__ __align__(16) float g_T3[400 * 260];   // stride-65 packed fc3^T (j pad 0)
__device__ int   g_colors[NV];
__device__ int   g_pp;              // (progress << 9) | nused  (release, for gates)
__device__ int   g_mbox[G];         // chain mailbox: (v<<18)|(chosen<<9)|nused
__device__ float g_lppp[G];
__device__ int   g_done[G];

// ---------------- smem layout (float indices) ----------------
#define S_H    0        // 8192  (16 x 512 gathered rows)
#define S_P1   8192     // 4096  (P1: 16x256; P2: 8x200; P3: 8x128/132 - reused)
#define S_PZ   12288    // 4096
#define S_NE   16384    // 512
#define S_H1   16896    // 512
#define S_H2   17408    // 512
#define S_LG   17920    // 260
#define S_A2   18180    // 512
#define S_B1   18692    // 512
#define S_B2   19204    // 512
#define S_B3   19716    // 512
#define S_CTF  20228    // 256
#define S_CTI  20484    // 256
#define S_E2   20740    // 32
#define S_RED  20772    // 32
#define S_SWM  20804    // 8
#define S_SWS  20812    // 8
#define S_SWI  20820    // 8 int
#define S_NBR  20828    // 16 int
#define S_NBRC 20844    // 16 int
#define S_GM   20860    // 4 float (K, L256, E256)
#define S_MB   20864    // 3 x u64 mbarriers (h1, h2, lg) + pad
#define S_TOT  20872
#define SMEMB  (S_TOT * 4)

__device__ __forceinline__ float wsum(float v) {
#pragma unroll
    for (int o = 16; o; o >>= 1) v += __shfl_xor_sync(0xffffffffu, v, o);
    return v;
}
__device__ __forceinline__ float wmax(float v) {
#pragma unroll
    for (int o = 16; o; o >>= 1) v = fmaxf(v, __shfl_xor_sync(0xffffffffu, v, o));
    return v;
}
__device__ __forceinline__ float dot4(float4 a, float4 b) {
    return a.x * b.x + a.y * b.y + a.z * b.z + a.w * b.w;
}
__device__ __forceinline__ int ld_acq(const int* p) {
    int v;
    asm volatile("ld.acquire.gpu.b32 %0, [%1];" : "=r"(v) : "l"(p) : "memory");
    return v;
}
__device__ __forceinline__ void st_rel(int* p, int v) {
    asm volatile("st.release.gpu.b32 [%0], %1;" :: "l"(p), "r"(v) : "memory");
}
__device__ __forceinline__ int ld_rlx(const int* p) {
    int v;
    asm volatile("ld.relaxed.gpu.b32 %0, [%1];" : "=r"(v) : "l"(p) : "memory");
    return v;
}
__device__ __forceinline__ void st_rlx(int* p, int v) {
    asm volatile("st.relaxed.gpu.b32 [%0], %1;" :: "l"(p), "r"(v) : "memory");
}
__device__ __forceinline__ uint32_t s2u(const void* p) {
    uint32_t a;
    asm("{ .reg .u64 t; cvta.to.shared.u64 t, %1; cvt.u32.u64 %0, t; }" : "=r"(a) : "l"(p));
    return a;
}
__device__ __forceinline__ uint32_t mapa_u32(uint32_t laddr, uint32_t rnk) {
    uint32_t r;
    asm("mapa.shared::cluster.u32 %0, %1, %2;" : "=r"(r) : "r"(laddr), "r"(rnk));
    return r;
}
__device__ __forceinline__ void sts_cl_f32(uint32_t a, float v) {
    asm volatile("st.shared::cluster.f32 [%0], %1;" :: "r"(a), "f"(v) : "memory");
}
__device__ __forceinline__ void mbar_init(uint32_t a, uint32_t cnt) {
    asm volatile("mbarrier.init.shared.b64 [%0], %1;" :: "r"(a), "r"(cnt) : "memory");
}
__device__ __forceinline__ void mbar_arrive_cl(uint32_t ra) {
    asm volatile("mbarrier.arrive.release.cluster.shared::cluster.b64 _, [%0];" :: "r"(ra) : "memory");
}
__device__ __forceinline__ void fence_cl() {
    asm volatile("fence.acq_rel.cluster;" ::: "memory");
}
__device__ __forceinline__ void fence_gpu() {
    asm volatile("fence.acq_rel.gpu;" ::: "memory");
}
#define MBAR_WAIT_CL(addr, par) do { \
    uint32_t _d; \
    asm volatile("{\n\t.reg .pred p;\n\t" \
        "mbarrier.try_wait.parity.acquire.cluster.shared::cta.b64 p, [%1], %2;\n\t" \
        "selp.b32 %0, 1, 0, p;\n\t}" : "=r"(_d) : "r"(addr), "r"(par) : "memory"); \
    if (!_d) { \
        asm volatile("{\n\t.reg .pred P1;\n\t" \
            "W%=:\n\t" \
            "mbarrier.try_wait.parity.acquire.cluster.shared::cta.b64 P1, [%0], %1, 0x989680;\n\t" \
            "@P1 bra.uni D%=;\n\t" \
            "bra.uni W%=;\n\t" \
            "D%=:\n\t}" :: "r"(addr), "r"(par) : "memory"); \
    } \
} while (0)
#define CLUSTER_SYNC() do { \
    asm volatile("barrier.cluster.arrive.aligned;" ::: "memory"); \
    asm volatile("barrier.cluster.wait.aligned;"   ::: "memory"); } while (0)

// backoff poll on g_pp until progress >= target (gate path only)
__device__ __forceinline__ int poll_pp(int target) {
    int pk = ld_acq(&g_pp);
    int d = target - (pk >> 9);
    while (d > 0) {
        if (d > 2) {
            int ns = d * 100; if (ns > 3000) ns = 3000;
            __nanosleep((unsigned)ns);
        }
        pk = ld_acq(&g_pp);
        d = target - (pk >> 9);
    }
    return pk;
}

// ---------------- init kernel (runs every launch) ----------------
__global__ void initk(const float* __restrict__ fc1w, const float* __restrict__ fc2w,
                      const float* __restrict__ fc3w) {
    int gt = blockIdx.x * blockDim.x + threadIdx.x;
    int GS = gridDim.x * blockDim.x;
    for (int d = gt; d < 512 * 512; d += GS) {
        int k = d >> 9, j = d & 511;
        g_T1[d] = fc1w[j * 512 + k];
    }
    for (int d = gt; d < 512 * 400; d += GS) {
        int c = d & 3, rest = d >> 2, j4 = rest % 100, k = rest / 100;
        g_T2[d] = fc2w[(j4 * 4 + c) * 512 + k];
    }
    for (int d = gt; d < 400 * 260; d += GS) {
        int c = d & 3, rest = d >> 2, j4 = rest % 65, k = rest / 65;
        int j = j4 * 4 + c;
        g_T3[d] = (j < NL) ? fc3w[j * 400 + k] : 0.f;
    }
    for (int i = gt; i < NV; i += GS) g_colors[i] = (i == 0) ? 0 : -1;
    for (int i = gt; i < 512; i += GS) g_z[i] = 0.f;
    if (gt < G) {
        g_done[gt] = 0; g_lppp[gt] = 0.f;
        g_mbox[gt] = (gt == 0) ? 1 : 0x7fffffff;   // v=0 commit: chosen=0, nused=1
    }
    if (gt == 0) g_pp = 1;                          // progress=0, nused=1
}

// column-GEMV partial: KQ k-steps (even), weights pre-offset, float4-stride STRIDE
template<int KQ, int STRIDE>
__device__ __forceinline__ float4 gemv_part(const float4* __restrict__ w,
                                            const float* __restrict__ x) {
    float4 e = make_float4(0.f, 0.f, 0.f, 0.f);
    float4 o = make_float4(0.f, 0.f, 0.f, 0.f);
#pragma unroll 8
    for (int k = 0; k < KQ; k += 2) {
        float x0 = x[k], x1 = x[k + 1];
        float4 w0 = __ldcg(w + (size_t)k * STRIDE);
        float4 w1 = __ldcg(w + (size_t)(k + 1) * STRIDE);
        e.x = fmaf(w0.x, x0, e.x); e.y = fmaf(w0.y, x0, e.y);
        e.z = fmaf(w0.z, x0, e.z); e.w = fmaf(w0.w, x0, e.w);
        o.x = fmaf(w1.x, x1, o.x); o.y = fmaf(w1.y, x1, o.y);
        o.z = fmaf(w1.z, x1, o.z); o.w = fmaf(w1.w, x1, o.w);
    }
    return make_float4(e.x + o.x, e.y + o.y, e.z + o.z, e.w + o.w);
}

__global__ void __launch_bounds__(TPB, 1) __cluster_dims__(2, 1, 1)
gc_main(const int* __restrict__ adj, const float* __restrict__ W,
        const float* __restrict__ a, const float* __restrict__ fc1w,
        const float* __restrict__ fc1b, const float* __restrict__ fc2w,
        const float* __restrict__ fc2b, const float* __restrict__ fc3w,
        const float* __restrict__ fc3b, const int* __restrict__ baseline,
        float* __restrict__ out, int out_size)
{
    extern __shared__ __align__(16) float sm[];
    int*   smi     = (int*)sm;
    float* sh_h    = sm + S_H;
    float* sh_p1   = sm + S_P1;
    float* sh_pz   = sm + S_PZ;
    float* sh_ne   = sm + S_NE;
    float* sh_h1   = sm + S_H1;
    float* sh_h2   = sm + S_H2;
    float* sh_lg   = sm + S_LG;
    float* sh_a2   = sm + S_A2;
    float* sh_b1   = sm + S_B1;
    float* sh_b2   = sm + S_B2;
    float* sh_b3   = sm + S_B3;
    float* sh_ctf  = sm + S_CTF;
    int*   sh_cti  = smi + S_CTI;
    float* sh_e2   = sm + S_E2;
    float* sh_red  = sm + S_RED;
    float* sh_swm  = sm + S_SWM;
    float* sh_sws  = sm + S_SWS;
    int*   sh_swi  = smi + S_SWI;
    int*   sh_nbr  = smi + S_NBR;
    int*   sh_nbrc = smi + S_NBRC;
    float* sh_gm   = sm + S_GM;

    const int pair = blockIdx.x >> 1;
    const int rk   = blockIdx.x & 1;
    const int peer = rk ^ 1;
    const int tid  = threadIdx.x;
    const int warp = tid >> 5, lane = tid & 31;
    const int j4  = tid & 63,  kp  = tid >> 6;     // P1/z: 64 groups x 16 parts, KQ=32
    const int j4b = tid % 50,  kpb = tid / 50;     // P2: 50 groups x 8 parts, KQ=64
    const int NGR = rk ? 33 : 32, base3 = rk ? 32 : 0;
    const int j4c = tid % NGR, kpc = tid / NGR;    // P3: 8 parts, KQ=50

    const uint32_t A_H1  = s2u(sh_h1);
    const uint32_t A_H2  = s2u(sh_h2);
    const uint32_t A_LG  = s2u(sh_lg);
    const uint32_t MB    = s2u(sm + S_MB);
    const uint32_t MB_H1 = MB, MB_H2 = MB + 8, MB_LG = MB + 16;

    float lpp = 0.f, regv = 0.f;
    int last_nn = 0, cprog = 0;

    if (tid < 512) {
        sh_a2[tid] = a[512 + tid];
        sh_b1[tid] = fc1b[tid];
        sh_b2[tid] = (tid < 400) ? fc2b[tid] : 0.f;
        sh_b3[tid] = (tid < NL)  ? fc3b[tid] : 0.f;
    }
    if (tid == 0) { mbar_init(MB_H1, 1); mbar_init(MB_H2, 1); mbar_init(MB_LG, 1); }
    __syncthreads();
    CLUSTER_SYNC();   // peer smem + mbarriers live before any dsmem traffic

    // Frobenius norms on the final-committing CTA (off the chain root; regv stays local)
    if (blockIdx.x == 2 * FINAL_PAIR) {
        float s[4] = {0.f, 0.f, 0.f, 0.f};
        for (int i = tid; i < 768 * 512; i += TPB) { float x = W[i];    s[0] += x * x; }
        for (int i = tid; i < 512 * 512; i += TPB) { float x = fc1w[i]; s[1] += x * x; }
        for (int i = tid; i < 400 * 512; i += TPB) { float x = fc2w[i]; s[2] += x * x; }
        for (int i = tid; i < 257 * 400; i += TPB) { float x = fc3w[i]; s[3] += x * x; }
#pragma unroll
        for (int m = 0; m < 4; m++) {
            float w = wsum(s[m]);
            __syncthreads();
            if (lane == 0) sh_red[warp] = w;
            __syncthreads();
            if (warp == 0) {
                float v2 = sh_red[lane];
                v2 = wsum(v2);
                if (lane == 0) sh_gm[0] = sqrtf(v2);
            }
            __syncthreads();
            regv += sh_gm[0];
            __syncthreads();
        }
    }
    if (blockIdx.x == 0 && tid == 0 && out_size > 0) out[0] = 0.f;

    int it = 0;
    // ======================= pipelined speculative scan (pair-split) =======================
    for (int v = 1 + pair; v < NV; v += G, ++it) {
        const int ph = it & 1;
        if (tid < 16) sh_nbr[tid] = __ldg(&adj[v * DEG + tid]);
        __syncthreads();

        // ---- gate ----
        if (tid == 0) {
            int maxu = -1;
#pragma unroll
            for (int t = 0; t < 16; t++) { int u = sh_nbr[t]; if (u < v && u > maxu) maxu = u; }
            if (maxu > cprog) cprog = poll_pp(maxu) >> 9;
        }
        __syncthreads();

        // ---- Stage A (replicated): 16 rows, 2 half-rows per warp ----
        {
            int r = warp & 15, hf = warp >> 4;
            int u = sh_nbr[r];
            float d2 = 0.f; int c = -1;
            float4* hrow = (float4*)(sh_h + r * 512);
            const float4* a24 = (const float4*)sh_a2;
            if (u < v) {
                c = __ldcg(&g_colors[u]);
                const float4* zp = (const float4*)(g_z + (size_t)u * 512);
                const float4* wp = ((unsigned)c < NPCC)
                                 ? (const float4*)(W + (size_t)(512 + c) * 512) : (const float4*)0;
#pragma unroll
                for (int i = 0; i < 2; i++) {
                    int idx = hf * 64 + lane + 32 * i;
                    float4 hv = __ldcg(zp + idx);
                    if (wp) { float4 wv = __ldg(wp + idx);
                              hv.x += wv.x; hv.y += wv.y; hv.z += wv.z; hv.w += wv.w; }
                    hrow[idx] = hv;
                    d2 += dot4(hv, a24[idx]);
                }
                d2 = wsum(d2);
            } else {
                float4 zr = make_float4(0.f, 0.f, 0.f, 0.f);
#pragma unroll
                for (int i = 0; i < 2; i++) hrow[hf * 64 + lane + 32 * i] = zr;
            }
            if (lane == 0) { sh_e2[2 * r + hf] = d2; if (hf == 0) sh_nbrc[r] = c; }
        }
        __syncthreads();

        // ---- softmax (warps 0-15, replicated) + ne = elu(attn @ h) ----
        if (warp < 16) {
            float ev;
            if (lane == 0) ev = 0.f;
            else if (lane < 17) {
                float t = sh_e2[2 * (lane - 1)] + sh_e2[2 * (lane - 1) + 1];
                ev = (t > 0.f) ? t : 0.2f * t;
            } else ev = NINF;
            float m = ev;
#pragma unroll
            for (int o = 16; o; o >>= 1) m = fmaxf(m, __shfl_xor_sync(0xffffffffu, m, o));
            float p = (lane < 17) ? expf(ev - m) : 0.f;
            float s = wsum(p);
            float attn = p / s;
            float acc = 0.f;
#pragma unroll
            for (int t = 1; t < 17; t++)
                acc += __shfl_sync(0xffffffffu, attn, t) * sh_h[(t - 1) * 512 + tid];
            sh_ne[tid] = (acc > 0.f) ? acc : expm1f(acc);
        }
        __syncthreads();

        // ---- P1 (fc1 half) + z half ----
        {
            float4 r1 = gemv_part<32, 128>((const float4*)g_T1 + (size_t)(kp * 32) * 128
                                               + rk * 64 + j4, sh_ne + kp * 32);
            float4 rz = gemv_part<32, 128>((const float4*)W + (size_t)(kp * 32) * 128
                                               + rk * 64 + j4, sh_ne + kp * 32);
            ((float4*)(sh_p1 + kp * 256))[j4] = r1;
            ((float4*)(sh_pz + kp * 256))[j4] = rz;
        }
        __syncthreads();
        if (tid < 256) {
            float s1 = 0.f, sz = 0.f;
#pragma unroll
            for (int q = 0; q < 16; q++) { s1 += sh_p1[q * 256 + tid]; sz += sh_pz[q * 256 + tid]; }
            int col = rk * 256 + tid;
            float h = s1 + sh_b1[col];
            h = (h > 0.f) ? h : 0.01f * h;
            sh_h1[col] = h;
            sts_cl_f32(mapa_u32(A_H1 + col * 4, peer), h);
            __stcg(&g_z[(size_t)v * 512 + col], sz);
        }
        __syncthreads();
        if (tid == 0) { fence_cl(); mbar_arrive_cl(mapa_u32(MB_H1, peer)); }
        MBAR_WAIT_CL(MB_H1, ph);

        // ---- P2 (fc2 half) over full h1 ----
        if (kpb < 8) {
            float4 r2 = gemv_part<64, 100>((const float4*)g_T2 + (size_t)(kpb * 64) * 100
                                               + rk * 50 + j4b, sh_h1 + kpb * 64);
            ((float4*)(sh_p1 + kpb * 200))[j4b] = r2;
        }
        __syncthreads();
        if (tid < 200) {
            float s1 = 0.f;
#pragma unroll
            for (int q = 0; q < 8; q++) s1 += sh_p1[q * 200 + tid];
            int col = rk * 200 + tid;
            float h = s1 + sh_b2[col];
            h = (h > 0.f) ? h : 0.01f * h;
            sh_h2[col] = h;
            sts_cl_f32(mapa_u32(A_H2 + col * 4, peer), h);
        }
        __syncthreads();
        if (tid == 0) { fence_cl(); mbar_arrive_cl(mapa_u32(MB_H2, peer)); }
        MBAR_WAIT_CL(MB_H2, ph);

        // ---- P3 (fc3 half) over full h2 ----
        if (kpc < 8) {
            float4 r3 = gemv_part<50, 65>((const float4*)g_T3 + (size_t)(kpc * 50) * 65
                                              + base3 + j4c, sh_h2 + kpc * 50);
            ((float4*)(sh_p1 + kpc * (NGR * 4)))[j4c] = r3;
        }
        __syncthreads();

        if (rk == 1) {
            // rank1: reduce its logit half, push to rank0, relay z-visibility via gpu fence
            if (tid < 132) {
                int col = 128 + tid;
                if (col < NL) {
                    float s1 = 0.f;
#pragma unroll
                    for (int q = 0; q < 8; q++) s1 += sh_p1[q * 132 + tid];
                    float L = s1 + sh_b3[col];
                    sts_cl_f32(mapa_u32(A_LG + col * 4, peer), L);
                }
            }
            __syncthreads();
            if (tid == 0) { fence_gpu(); mbar_arrive_cl(mapa_u32(MB_LG, peer)); }
            // no wait — proceed to next vertex
        } else {
            // rank0: own half, wait peer half, tables, commit
            if (tid < 128) {
                float s1 = 0.f;
#pragma unroll
                for (int q = 0; q < 8; q++) s1 += sh_p1[q * 128 + tid];
                sh_lg[tid] = s1 + sh_b3[tid];
            }
            __syncthreads();
            MBAR_WAIT_CL(MB_LG, ph);

            float L = (tid < NL) ? sh_lg[tid] : NINF;
            bool am = false;
            if (tid < NL) {
#pragma unroll
                for (int t = 0; t < 16; t++) am |= (sh_nbrc[t] == tid);
            }
            // K = unmasked max over all 257
            {
                float km = wmax(L);
                if (lane == 0) sh_red[warp] = km;
            }
            __syncthreads();
            if (warp == 0) {
                float v2 = sh_red[lane];
                v2 = wmax(v2);
                if (lane == 0) sh_gm[0] = v2;
            }
            if (tid == 256) sh_gm[1] = L;
            __syncthreads();
            const float K = sh_gm[0];

            // prefix scan over j<256 (adjacency pre-masked)
            float v_ = NINF, e_ = 0.f; int i_ = tid;
            if (tid < 256) {
                v_ = am ? NINF : L;
                e_ = am ? 0.f : expf(L - K);
#pragma unroll
                for (int o = 1; o < 32; o <<= 1) {
                    float pv = __shfl_up_sync(0xffffffffu, v_, o);
                    int   pi = __shfl_up_sync(0xffffffffu, i_, o);
                    float pe = __shfl_up_sync(0xffffffffu, e_, o);
                    if (lane >= o) { if (pv >= v_) { v_ = pv; i_ = pi; } e_ += pe; }
                }
                if (lane == 31) { sh_swm[warp] = v_; sh_swi[warp] = i_; sh_sws[warp] = e_; }
            }
            if (tid == 256) sh_gm[2] = expf(L - K);
            __syncthreads();
            if (tid < 256) {
                float bm = NINF; int bi = 0; float bs = 0.f;
#pragma unroll
                for (int w2 = 0; w2 < 8; w2++) {
                    if (w2 < warp) {
                        float tm = sh_swm[w2];
                        if (tm > bm) { bm = tm; bi = sh_swi[w2]; }
                        bs += sh_sws[w2];
                    }
                }
                if (bm >= v_) { v_ = bm; i_ = bi; }   // earlier warp wins ties
                e_ += bs;
                int   n      = tid + 1;
                float l2     = sh_gm[1];
                float e2     = sh_gm[2];
                int   isnew  = (l2 > v_) ? 1 : 0;     // lower index wins ties
                float gmax   = isnew ? l2 : v_;
                int   chosen = isnew ? n : i_;
                int   nn     = n + isnew;
                float maxp   = expf(gmax - K) / (e_ + e2);
                sh_ctf[tid] = logf(maxp + 1e-8f) + 18.420680743952367f;
                sh_cti[tid] = (chosen << 9) | nn;
            }
            __syncthreads();

            // commit: spin own mailbox, table lookup, relay
            if (tid == 0) {
                int w;
                do { w = ld_rlx(&g_mbox[pair]); } while ((w >> 18) != v - 1);
                int n  = w & 511;
                int ci = sh_cti[n - 1];
                int chosen = ci >> 9, nn = ci & 511;
                st_rlx(&g_mbox[v & (G - 1)], (v << 18) | ci);   // chain hop
                __stcg(&g_colors[v], chosen);
                if (v < out_size) out[v] = (float)chosen;
                lpp += sh_ctf[n - 1];
                st_rel(&g_pp, (v << 9) | nn);        // gates: orders colors/z/out
                cprog = v;
                last_nn = nn;
            }
            __syncthreads();
        }
    }

    // ---------------- finalize ----------------
    if (rk == 0 && tid == 0) {
        g_lppp[pair] = lpp;
        st_rel(&g_done[pair], 1);
        if (pair == FINAL_PAIR) {
            float tot = 0.f;
            for (int r = 0; r < G; r++) {
                while (ld_acq(&g_done[r]) == 0) __nanosleep(200);
                tot += __ldcg(&g_lppp[r]);
            }
            if (out_size > NV) {
                float loss = ((float)last_nn - (float)baseline[0]) * tot / (float)NV
                           + 0.05f * regv;
                out[NV] = loss;
            }
        }
    }
    CLUSTER_SYNC();   // no CTA exits while peer dsmem ops may target it
}

extern "C" void kernel_launch(void* const* d_in, const int* in_sizes, int n_in,
                              void* d_out, int out_size) {
    (void)in_sizes; (void)n_in;
    const int*   adj  = (const int*)d_in[0];
    const float* W    = (const float*)d_in[1];
    const float* a    = (const float*)d_in[2];
    const float* fc1w = (const float*)d_in[3];
    const float* fc1b = (const float*)d_in[4];
    const float* fc2w = (const float*)d_in[5];
    const float* fc2b = (const float*)d_in[6];
    const float* fc3w = (const float*)d_in[7];
    const float* fc3b = (const float*)d_in[8];
    const int*   bl   = (const int*)d_in[9];
    float* out = (float*)d_out;

    static int smem_set = 0;
    if (!smem_set) {
        cudaFuncSetAttribute(gc_main, cudaFuncAttributeMaxDynamicSharedMemorySize, SMEMB);
        smem_set = 1;
    }
    initk<<<128, 256>>>(fc1w, fc2w, fc3w);
    gc_main<<<2 * G, TPB, SMEMB>>>(adj, W, a, fc1w, fc1b, fc2w, fc2b,
                                   fc3w, fc3b, bl, out, out_size);
}

// round 15
// speedup vs baseline: 10.2140x; 1.1023x over previous
#include <cuda_runtime.h>
#include <math.h>
#include <stdint.h>

#define NV   8192
#define DEG  16
#define NPCC 256
#define NL   257
#define G    64        // pairs
#define TPB  512
#define NINF (-INFINITY)
#define FINAL_PAIR ((NV - 2) % G)   // 62

// ---------------- persistent device scratch ----------------
__device__ __align__(16) float g_z[(size_t)NV * 512];
__device__ __align__(16) float g_T1[512 * 512];   // fc1^T interleaved [k][j4][c]
__device__ __align__(16) float g_T2[512 * 400];   // stride-100 packed fc2^T
__device__ __align__(16) float g_T3[400 * 260];   // stride-65 packed fc3^T (j pad 0)
__device__ int   g_colors[NV];
__device__ int   g_pp;              // (progress << 9) | nused  (release, for gates)
__device__ int   g_mbox[G];         // chain mailbox: (v<<18)|(chosen<<9)|nused
__device__ float g_lppp[G];
__device__ int   g_done[G];

// ---------------- smem layout (float indices) ----------------
#define S_H    0        // 8192  (16 x 512 gathered rows)
#define S_P1   8192     // 2048  (P1: 8x256; P2: 8x200; P3: 8x132 - reused)
#define S_PZ   10240    // 2048
#define S_NE   12288    // 512
#define S_H1   12800    // 512
#define S_H2   13312    // 512
#define S_LG   13824    // 260
#define S_A2   14084    // 512
#define S_B1   14596    // 512
#define S_B2   15108    // 512
#define S_B3   15620    // 512
#define S_CTF  16132    // 256
#define S_CTI  16388    // 256
#define S_E2   16644    // 16
#define S_RED  16660    // 16
#define S_SWM  16676    // 8
#define S_SWS  16684    // 8
#define S_SWI  16692    // 8 int
#define S_NBR  16700    // 16 int
#define S_NBRC 16716    // 16 int
#define S_GM   16732    // 4 float (K, L256, E256)
#define S_MB   16736    // 3 x u64 mbarriers (h1, h2, lg)
#define S_TOT  16744
#define SMEMB  (S_TOT * 4)

__device__ __forceinline__ float wsum(float v) {
#pragma unroll
    for (int o = 16; o; o >>= 1) v += __shfl_xor_sync(0xffffffffu, v, o);
    return v;
}
__device__ __forceinline__ float wmax(float v) {
#pragma unroll
    for (int o = 16; o; o >>= 1) v = fmaxf(v, __shfl_xor_sync(0xffffffffu, v, o));
    return v;
}
__device__ __forceinline__ float dot4(float4 a, float4 b) {
    return a.x * b.x + a.y * b.y + a.z * b.z + a.w * b.w;
}
__device__ __forceinline__ int ld_acq(const int* p) {
    int v;
    asm volatile("ld.acquire.gpu.b32 %0, [%1];" : "=r"(v) : "l"(p) : "memory");
    return v;
}
__device__ __forceinline__ void st_rel(int* p, int v) {
    asm volatile("st.release.gpu.b32 [%0], %1;" :: "l"(p), "r"(v) : "memory");
}
__device__ __forceinline__ int ld_rlx(const int* p) {
    int v;
    asm volatile("ld.relaxed.gpu.b32 %0, [%1];" : "=r"(v) : "l"(p) : "memory");
    return v;
}
__device__ __forceinline__ void st_rlx(int* p, int v) {
    asm volatile("st.relaxed.gpu.b32 [%0], %1;" :: "l"(p), "r"(v) : "memory");
}
__device__ __forceinline__ uint32_t s2u(const void* p) {
    uint32_t a;
    asm("{ .reg .u64 t; cvta.to.shared.u64 t, %1; cvt.u32.u64 %0, t; }" : "=r"(a) : "l"(p));
    return a;
}
__device__ __forceinline__ uint32_t mapa_u32(uint32_t laddr, uint32_t rnk) {
    uint32_t r;
    asm("mapa.shared::cluster.u32 %0, %1, %2;" : "=r"(r) : "r"(laddr), "r"(rnk));
    return r;
}
__device__ __forceinline__ void sts_cl_f32(uint32_t a, float v) {
    asm volatile("st.shared::cluster.f32 [%0], %1;" :: "r"(a), "f"(v) : "memory");
}
__device__ __forceinline__ void mbar_init(uint32_t a, uint32_t cnt) {
    asm volatile("mbarrier.init.shared.b64 [%0], %1;" :: "r"(a), "r"(cnt) : "memory");
}
__device__ __forceinline__ void mbar_arrive_cl(uint32_t ra) {
    asm volatile("mbarrier.arrive.release.cluster.shared::cluster.b64 _, [%0];" :: "r"(ra) : "memory");
}
__device__ __forceinline__ void fence_cl() {
    asm volatile("fence.acq_rel.cluster;" ::: "memory");
}
__device__ __forceinline__ void fence_gpu() {
    asm volatile("fence.acq_rel.gpu;" ::: "memory");
}
#define MBAR_WAIT_CL(addr, par) do { \
    uint32_t _d; \
    asm volatile("{\n\t.reg .pred p;\n\t" \
        "mbarrier.try_wait.parity.acquire.cluster.shared::cta.b64 p, [%1], %2;\n\t" \
        "selp.b32 %0, 1, 0, p;\n\t}" : "=r"(_d) : "r"(addr), "r"(par) : "memory"); \
    if (!_d) { \
        asm volatile("{\n\t.reg .pred P1;\n\t" \
            "W%=:\n\t" \
            "mbarrier.try_wait.parity.acquire.cluster.shared::cta.b64 P1, [%0], %1, 0x989680;\n\t" \
            "@P1 bra.uni D%=;\n\t" \
            "bra.uni W%=;\n\t" \
            "D%=:\n\t}" :: "r"(addr), "r"(par) : "memory"); \
    } \
} while (0)
#define CLUSTER_SYNC() do { \
    asm volatile("barrier.cluster.arrive.aligned;" ::: "memory"); \
    asm volatile("barrier.cluster.wait.aligned;"   ::: "memory"); } while (0)

// backoff poll on g_pp until progress >= target (gate path only)
__device__ __forceinline__ int poll_pp(int target) {
    int pk = ld_acq(&g_pp);
    int d = target - (pk >> 9);
    while (d > 0) {
        if (d > 2) {
            int ns = d * 100; if (ns > 3000) ns = 3000;
            __nanosleep((unsigned)ns);
        }
        pk = ld_acq(&g_pp);
        d = target - (pk >> 9);
    }
    return pk;
}

// ---------------- init kernel (runs every launch) ----------------
__global__ void initk(const float* __restrict__ fc1w, const float* __restrict__ fc2w,
                      const float* __restrict__ fc3w) {
    int gt = blockIdx.x * blockDim.x + threadIdx.x;
    int GS = gridDim.x * blockDim.x;
    for (int d = gt; d < 512 * 512; d += GS) {
        int k = d >> 9, j = d & 511;
        g_T1[d] = fc1w[j * 512 + k];
    }
    for (int d = gt; d < 512 * 400; d += GS) {
        int c = d & 3, rest = d >> 2, j4 = rest % 100, k = rest / 100;
        g_T2[d] = fc2w[(j4 * 4 + c) * 512 + k];
    }
    for (int d = gt; d < 400 * 260; d += GS) {
        int c = d & 3, rest = d >> 2, j4 = rest % 65, k = rest / 65;
        int j = j4 * 4 + c;
        g_T3[d] = (j < NL) ? fc3w[j * 400 + k] : 0.f;
    }
    for (int i = gt; i < NV; i += GS) g_colors[i] = (i == 0) ? 0 : -1;
    for (int i = gt; i < 512; i += GS) g_z[i] = 0.f;
    if (gt < G) {
        g_done[gt] = 0; g_lppp[gt] = 0.f;
        g_mbox[gt] = (gt == 0) ? 1 : 0x7fffffff;   // v=0 commit: chosen=0, nused=1
    }
    if (gt == 0) g_pp = 1;                          // progress=0, nused=1
}

// column-GEMV partial: KQ k-steps (mult of 4), weights pre-offset, float4-stride STRIDE
template<int KQ, int STRIDE>
__device__ __forceinline__ float4 gemv_part(const float4* __restrict__ w,
                                            const float* __restrict__ x) {
    float4 e = make_float4(0.f, 0.f, 0.f, 0.f);
    float4 o = make_float4(0.f, 0.f, 0.f, 0.f);
#pragma unroll 16
    for (int k = 0; k < KQ; k += 2) {
        float x0 = x[k], x1 = x[k + 1];
        float4 w0 = __ldcg(w + (size_t)k * STRIDE);
        float4 w1 = __ldcg(w + (size_t)(k + 1) * STRIDE);
        e.x = fmaf(w0.x, x0, e.x); e.y = fmaf(w0.y, x0, e.y);
        e.z = fmaf(w0.z, x0, e.z); e.w = fmaf(w0.w, x0, e.w);
        o.x = fmaf(w1.x, x1, o.x); o.y = fmaf(w1.y, x1, o.y);
        o.z = fmaf(w1.z, x1, o.z); o.w = fmaf(w1.w, x1, o.w);
    }
    return make_float4(e.x + o.x, e.y + o.y, e.z + o.z, e.w + o.w);
}

__global__ void __launch_bounds__(TPB, 1) __cluster_dims__(2, 1, 1)
gc_main(const int* __restrict__ adj, const float* __restrict__ W,
        const float* __restrict__ a, const float* __restrict__ fc1w,
        const float* __restrict__ fc1b, const float* __restrict__ fc2w,
        const float* __restrict__ fc2b, const float* __restrict__ fc3w,
        const float* __restrict__ fc3b, const int* __restrict__ baseline,
        float* __restrict__ out, int out_size)
{
    extern __shared__ __align__(16) float sm[];
    int*   smi     = (int*)sm;
    float* sh_h    = sm + S_H;
    float* sh_p1   = sm + S_P1;
    float* sh_pz   = sm + S_PZ;
    float* sh_ne   = sm + S_NE;
    float* sh_h1   = sm + S_H1;
    float* sh_h2   = sm + S_H2;
    float* sh_lg   = sm + S_LG;
    float* sh_a2   = sm + S_A2;
    float* sh_b1   = sm + S_B1;
    float* sh_b2   = sm + S_B2;
    float* sh_b3   = sm + S_B3;
    float* sh_ctf  = sm + S_CTF;
    int*   sh_cti  = smi + S_CTI;
    float* sh_e2   = sm + S_E2;
    float* sh_red  = sm + S_RED;
    float* sh_swm  = sm + S_SWM;
    float* sh_sws  = sm + S_SWS;
    int*   sh_swi  = smi + S_SWI;
    int*   sh_nbr  = smi + S_NBR;
    int*   sh_nbrc = smi + S_NBRC;
    float* sh_gm   = sm + S_GM;

    const int pair = blockIdx.x >> 1;
    const int rk   = blockIdx.x & 1;
    const int peer = rk ^ 1;
    const int tid  = threadIdx.x;
    const int warp = tid >> 5, lane = tid & 31;
    const int j4  = tid & 63,  kp  = tid >> 6;     // P1/z: 64 groups x 8 parts, KQ=64
    const int j4b = tid % 50,  kpb = tid / 50;     // P2: 50 groups x 8 parts (400 thr), KQ=64
    const int NGR = rk ? 33 : 32, base3 = rk ? 32 : 0;
    const int j4c = tid % NGR, kpc = tid / NGR;    // P3: NGR groups x 8 parts, KQ=50

    const uint32_t A_H1  = s2u(sh_h1);
    const uint32_t A_H2  = s2u(sh_h2);
    const uint32_t A_LG  = s2u(sh_lg);
    const uint32_t MB    = s2u(sm + S_MB);
    const uint32_t MB_H1 = MB, MB_H2 = MB + 8, MB_LG = MB + 16;

    float lpp = 0.f, regv = 0.f;
    int last_nn = 0, cprog = 0;

    {
        sh_a2[tid] = a[512 + tid];
        sh_b1[tid] = fc1b[tid];
        sh_b2[tid] = (tid < 400) ? fc2b[tid] : 0.f;
        sh_b3[tid] = (tid < NL)  ? fc3b[tid] : 0.f;
    }
    if (tid == 0) { mbar_init(MB_H1, 1); mbar_init(MB_H2, 1); mbar_init(MB_LG, 1); }
    __syncthreads();
    CLUSTER_SYNC();   // peer smem + mbarriers live before any dsmem traffic

    // Frobenius norms on the final-committing CTA (off the chain root; regv stays local)
    if (blockIdx.x == 2 * FINAL_PAIR) {
        float s[4] = {0.f, 0.f, 0.f, 0.f};
        for (int i = tid; i < 768 * 512; i += TPB) { float x = W[i];    s[0] += x * x; }
        for (int i = tid; i < 512 * 512; i += TPB) { float x = fc1w[i]; s[1] += x * x; }
        for (int i = tid; i < 400 * 512; i += TPB) { float x = fc2w[i]; s[2] += x * x; }
        for (int i = tid; i < 257 * 400; i += TPB) { float x = fc3w[i]; s[3] += x * x; }
#pragma unroll
        for (int m = 0; m < 4; m++) {
            float w = wsum(s[m]);
            __syncthreads();
            if (lane == 0) sh_red[warp] = w;
            __syncthreads();
            if (warp == 0) {
                float v2 = (lane < 16) ? sh_red[lane] : 0.f;
                v2 = wsum(v2);
                if (lane == 0) sh_gm[0] = sqrtf(v2);
            }
            __syncthreads();
            regv += sh_gm[0];
            __syncthreads();
        }
    }
    if (blockIdx.x == 0 && tid == 0 && out_size > 0) out[0] = 0.f;

    int it = 0;
    // ======================= pipelined speculative scan (pair-split) =======================
    for (int v = 1 + pair; v < NV; v += G, ++it) {
        const int ph = it & 1;
        if (tid < 16) sh_nbr[tid] = __ldg(&adj[v * DEG + tid]);
        __syncthreads();

        // ---- gate ----
        if (tid == 0) {
            int maxu = -1;
#pragma unroll
            for (int t = 0; t < 16; t++) { int u = sh_nbr[t]; if (u < v && u > maxu) maxu = u; }
            if (maxu > cprog) cprog = poll_pp(maxu) >> 9;
        }
        __syncthreads();

        // ---- Stage A (replicated): one full row per warp ----
        {
            int u = sh_nbr[warp];
            float d2 = 0.f; int c = -1;
            float4* hrow = (float4*)(sh_h + warp * 512);
            const float4* a24 = (const float4*)sh_a2;
            if (u < v) {
                c = __ldcg(&g_colors[u]);
                const float4* zp = (const float4*)(g_z + (size_t)u * 512);
                const float4* wp = ((unsigned)c < NPCC)
                                 ? (const float4*)(W + (size_t)(512 + c) * 512) : (const float4*)0;
#pragma unroll
                for (int i = 0; i < 4; i++) {
                    int idx = lane + 32 * i;
                    float4 hv = __ldcg(zp + idx);
                    if (wp) { float4 wv = __ldg(wp + idx);
                              hv.x += wv.x; hv.y += wv.y; hv.z += wv.z; hv.w += wv.w; }
                    hrow[idx] = hv;
                    d2 += dot4(hv, a24[idx]);
                }
                d2 = wsum(d2);
            } else {
                float4 zr = make_float4(0.f, 0.f, 0.f, 0.f);
#pragma unroll
                for (int i = 0; i < 4; i++) hrow[lane + 32 * i] = zr;
            }
            if (lane == 0) { sh_e2[warp] = d2; sh_nbrc[warp] = c; }
        }
        __syncthreads();

        // ---- softmax (replicated per warp) + ne = elu(attn @ h) ----
        {
            float ev;
            if (lane == 0) ev = 0.f;
            else if (lane < 17) {
                float t = sh_e2[lane - 1];
                ev = (t > 0.f) ? t : 0.2f * t;
            } else ev = NINF;
            float m = ev;
#pragma unroll
            for (int o = 16; o; o >>= 1) m = fmaxf(m, __shfl_xor_sync(0xffffffffu, m, o));
            float p = (lane < 17) ? expf(ev - m) : 0.f;
            float s = wsum(p);
            float attn = p / s;
            float acc = 0.f;
#pragma unroll
            for (int t = 1; t < 17; t++)
                acc += __shfl_sync(0xffffffffu, attn, t) * sh_h[(t - 1) * 512 + tid];
            sh_ne[tid] = (acc > 0.f) ? acc : expm1f(acc);
        }
        __syncthreads();

        // ---- P1 (fc1 half) + z half : KQ=64, 8 parts ----
        {
            float4 r1 = gemv_part<64, 128>((const float4*)g_T1 + (size_t)(kp * 64) * 128
                                               + rk * 64 + j4, sh_ne + kp * 64);
            float4 rz = gemv_part<64, 128>((const float4*)W + (size_t)(kp * 64) * 128
                                               + rk * 64 + j4, sh_ne + kp * 64);
            ((float4*)(sh_p1 + kp * 256))[j4] = r1;
            ((float4*)(sh_pz + kp * 256))[j4] = rz;
        }
        __syncthreads();
        if (tid < 256) {
            float s1 = 0.f, sz = 0.f;
#pragma unroll
            for (int q = 0; q < 8; q++) { s1 += sh_p1[q * 256 + tid]; sz += sh_pz[q * 256 + tid]; }
            int col = rk * 256 + tid;
            float h = s1 + sh_b1[col];
            h = (h > 0.f) ? h : 0.01f * h;
            sh_h1[col] = h;
            sts_cl_f32(mapa_u32(A_H1 + col * 4, peer), h);
            __stcg(&g_z[(size_t)v * 512 + col], sz);
        }
        __syncthreads();
        if (tid == 0) { fence_cl(); mbar_arrive_cl(mapa_u32(MB_H1, peer)); }
        MBAR_WAIT_CL(MB_H1, ph);

        // ---- P2 (fc2 half) over full h1 ----
        if (kpb < 8) {
            float4 r2 = gemv_part<64, 100>((const float4*)g_T2 + (size_t)(kpb * 64) * 100
                                               + rk * 50 + j4b, sh_h1 + kpb * 64);
            ((float4*)(sh_p1 + kpb * 200))[j4b] = r2;
        }
        __syncthreads();
        if (tid < 200) {
            float s1 = 0.f;
#pragma unroll
            for (int q = 0; q < 8; q++) s1 += sh_p1[q * 200 + tid];
            int col = rk * 200 + tid;
            float h = s1 + sh_b2[col];
            h = (h > 0.f) ? h : 0.01f * h;
            sh_h2[col] = h;
            sts_cl_f32(mapa_u32(A_H2 + col * 4, peer), h);
        }
        __syncthreads();
        if (tid == 0) { fence_cl(); mbar_arrive_cl(mapa_u32(MB_H2, peer)); }
        MBAR_WAIT_CL(MB_H2, ph);

        // ---- P3 (fc3 half) over full h2 ----
        if (kpc < 8) {
            float4 r3 = gemv_part<50, 65>((const float4*)g_T3 + (size_t)(kpc * 50) * 65
                                              + base3 + j4c, sh_h2 + kpc * 50);
            ((float4*)(sh_p1 + kpc * (NGR * 4)))[j4c] = r3;
        }
        __syncthreads();

        if (rk == 1) {
            // rank1: reduce its logit half, push to rank0, relay z-visibility via gpu fence
            if (tid < 132) {
                int col = 128 + tid;
                if (col < NL) {
                    float s1 = 0.f;
#pragma unroll
                    for (int q = 0; q < 8; q++) s1 += sh_p1[q * 132 + tid];
                    float L = s1 + sh_b3[col];
                    sts_cl_f32(mapa_u32(A_LG + col * 4, peer), L);
                }
            }
            __syncthreads();
            if (tid == 0) { fence_gpu(); mbar_arrive_cl(mapa_u32(MB_LG, peer)); }
            // no wait — proceed to next vertex
        } else {
            // rank0: own half, wait peer half, tables, commit
            if (tid < 128) {
                float s1 = 0.f;
#pragma unroll
                for (int q = 0; q < 8; q++) s1 += sh_p1[q * 128 + tid];
                sh_lg[tid] = s1 + sh_b3[tid];
            }
            __syncthreads();
            MBAR_WAIT_CL(MB_LG, ph);

            float L = (tid < NL) ? sh_lg[tid] : NINF;
            bool am = false;
            if (tid < NL) {
#pragma unroll
                for (int t = 0; t < 16; t++) am |= (sh_nbrc[t] == tid);
            }
            // K = unmasked max over all 257
            {
                float km = wmax(L);
                if (lane == 0) sh_red[warp] = km;
            }
            __syncthreads();
            if (warp == 0) {
                float v2 = (lane < 16) ? sh_red[lane] : NINF;
                v2 = wmax(v2);
                if (lane == 0) sh_gm[0] = v2;
            }
            if (tid == 256) sh_gm[1] = L;
            __syncthreads();
            const float K = sh_gm[0];

            // prefix scan over j<256 (adjacency pre-masked)
            float v_ = NINF, e_ = 0.f; int i_ = tid;
            if (tid < 256) {
                v_ = am ? NINF : L;
                e_ = am ? 0.f : expf(L - K);
#pragma unroll
                for (int o = 1; o < 32; o <<= 1) {
                    float pv = __shfl_up_sync(0xffffffffu, v_, o);
                    int   pi = __shfl_up_sync(0xffffffffu, i_, o);
                    float pe = __shfl_up_sync(0xffffffffu, e_, o);
                    if (lane >= o) { if (pv >= v_) { v_ = pv; i_ = pi; } e_ += pe; }
                }
                if (lane == 31) { sh_swm[warp] = v_; sh_swi[warp] = i_; sh_sws[warp] = e_; }
            }
            if (tid == 256) sh_gm[2] = expf(L - K);
            __syncthreads();
            if (tid < 256) {
                float bm = NINF; int bi = 0; float bs = 0.f;
#pragma unroll
                for (int w2 = 0; w2 < 8; w2++) {
                    if (w2 < warp) {
                        float tm = sh_swm[w2];
                        if (tm > bm) { bm = tm; bi = sh_swi[w2]; }
                        bs += sh_sws[w2];
                    }
                }
                if (bm >= v_) { v_ = bm; i_ = bi; }   // earlier warp wins ties
                e_ += bs;
                int   n      = tid + 1;
                float l2     = sh_gm[1];
                float e2     = sh_gm[2];
                int   isnew  = (l2 > v_) ? 1 : 0;     // lower index wins ties
                float gmax   = isnew ? l2 : v_;
                int   chosen = isnew ? n : i_;
                int   nn     = n + isnew;
                float maxp   = expf(gmax - K) / (e_ + e2);
                sh_ctf[tid] = logf(maxp + 1e-8f) + 18.420680743952367f;
                sh_cti[tid] = (chosen << 9) | nn;
            }
            __syncthreads();

            // commit: spin own mailbox, table lookup, relay
            if (tid == 0) {
                int w;
                do { w = ld_rlx(&g_mbox[pair]); } while ((w >> 18) != v - 1);
                int n  = w & 511;
                int ci = sh_cti[n - 1];
                int chosen = ci >> 9, nn = ci & 511;
                st_rlx(&g_mbox[v & (G - 1)], (v << 18) | ci);   // chain hop
                __stcg(&g_colors[v], chosen);
                if (v < out_size) out[v] = (float)chosen;
                lpp += sh_ctf[n - 1];
                st_rel(&g_pp, (v << 9) | nn);        // gates: orders colors/z/out
                cprog = v;
                last_nn = nn;
            }
            __syncthreads();
        }
    }

    // ---------------- finalize ----------------
    if (rk == 0 && tid == 0) {
        g_lppp[pair] = lpp;
        st_rel(&g_done[pair], 1);
        if (pair == FINAL_PAIR) {
            float tot = 0.f;
            for (int r = 0; r < G; r++) {
                while (ld_acq(&g_done[r]) == 0) __nanosleep(200);
                tot += __ldcg(&g_lppp[r]);
            }
            if (out_size > NV) {
                float loss = ((float)last_nn - (float)baseline[0]) * tot / (float)NV
                           + 0.05f * regv;
                out[NV] = loss;
            }
        }
    }
    CLUSTER_SYNC();   // no CTA exits while peer dsmem ops may target it
}

extern "C" void kernel_launch(void* const* d_in, const int* in_sizes, int n_in,
                              void* d_out, int out_size) {
    (void)in_sizes; (void)n_in;
    const int*   adj  = (const int*)d_in[0];
    const float* W    = (const float*)d_in[1];
    const float* a    = (const float*)d_in[2];
    const float* fc1w = (const float*)d_in[3];
    const float* fc1b = (const float*)d_in[4];
    const float* fc2w = (const float*)d_in[5];
    const float* fc2b = (const float*)d_in[6];
    const float* fc3w = (const float*)d_in[7];
    const float* fc3b = (const float*)d_in[8];
    const int*   bl   = (const int*)d_in[9];
    float* out = (float*)d_out;

    static int smem_set = 0;
    if (!smem_set) {
        cudaFuncSetAttribute(gc_main, cudaFuncAttributeMaxDynamicSharedMemorySize, SMEMB);
        smem_set = 1;
    }
    initk<<<128, 256>>>(fc1w, fc2w, fc3w);
    gc_main<<<2 * G, TPB, SMEMB>>>(adj, W, a, fc1w, fc1b, fc2w, fc2b,
                                   fc3w, fc3b, bl, out, out_size);
}